// round 3
// baseline (speedup 1.0000x reference)
#include <cuda_runtime.h>
#include <math.h>

#define C        64
#define HH       256
#define WW       256
#define NPIX     65536            // HH*WW
#define BATCH    2
#define HEADS    8
#define KVSZ     648              // 72*8 + 72 per (b,h)

// -------- scratch (device globals: allocation-free at launch time) --------
__device__ float g_q [BATCH*C*NPIX];
__device__ float g_k [BATCH*C*NPIX];
__device__ float g_v [BATCH*C*NPIX];
__device__ float g_o [BATCH*C*NPIX];
__device__ float g_x1[BATCH*C*NPIX];
__device__ float g_h1[BATCH*C*NPIX];
__device__ float g_h2[BATCH*C*NPIX];
__device__ float g_kv[BATCH*HEADS*KVSZ];

__device__ __forceinline__ float gelu_exact(float v) {
    return 0.5f * v * (1.0f + erff(v * 0.7071067811865476f));
}

// ---------------------------------------------------------------
// zero the kv accumulator
// ---------------------------------------------------------------
__global__ void zero_kv_kernel() {
    int i = blockIdx.x * blockDim.x + threadIdx.x;
    if (i < BATCH*HEADS*KVSZ) g_kv[i] = 0.0f;
}

// ---------------------------------------------------------------
// qkv = 1x1 conv (64 -> 192) + bias ; relu on q,k
// one thread = one pixel, x row kept in registers.
// weights staged through ONE 16KB smem buffer in 3 passes
// (q, k, v) to stay under the 48KB static-smem limit.
// ---------------------------------------------------------------
__global__ __launch_bounds__(256)
void qkv_kernel(const float* __restrict__ x,
                const float* __restrict__ w,
                const float* __restrict__ bias) {
    __shared__ float ws[C*C];     // 16 KB
    __shared__ float bs[C];

    int pix = blockIdx.x * 256 + threadIdx.x;      // 0 .. BATCH*NPIX-1 (exact grid)
    int b   = pix >> 16;
    int n   = pix & (NPIX - 1);

    const float* xb = x + (long)b*C*NPIX + n;
    float xv[C];
    #pragma unroll
    for (int c = 0; c < C; c++) xv[c] = xb[(long)c*NPIX];

    long obase = (long)b*C*NPIX + n;

    #pragma unroll 1
    for (int part = 0; part < 3; part++) {
        __syncthreads();
        for (int i = threadIdx.x; i < C*C; i += 256) ws[i] = w[part*C*C + i];
        if (threadIdx.x < C) bs[threadIdx.x] = bias[part*C + threadIdx.x];
        __syncthreads();

        float* outp = (part == 0) ? g_q : (part == 1) ? g_k : g_v;
        bool do_relu = (part < 2);

        #pragma unroll 1
        for (int oc = 0; oc < C; oc++) {
            float a = bs[oc];
            const float* wr = ws + oc*C;
            #pragma unroll
            for (int c2 = 0; c2 < C; c2++) a = fmaf(wr[c2], xv[c2], a);
            if (do_relu) a = fmaxf(a, 0.0f);
            outp[obase + (long)oc*NPIX] = a;
        }
    }
}

// ---------------------------------------------------------------
// kv[b,h,d,e] = sum_n k_unfold[d,n] * v[e,n]  ;  ksum[b,h,d] = sum_n k_unfold[d,n]
// d = cl*9 + (i*3+j), offset (i-1, j-1), zero-padded.
// warp w handles cl=w; lanes sweep columns; register accumulators,
// warp shfl reduction, then 81 atomicAdds per warp.
// ---------------------------------------------------------------
#define KV_ROWS 16
__global__ __launch_bounds__(256)
void kv_kernel() {
    int bh = blockIdx.y;                  // 0..15
    int b  = bh >> 3;
    int h  = bh & 7;
    int warp = threadIdx.x >> 5;
    int lane = threadIdx.x & 31;
    int cl = warp;                        // 8 warps -> 8 cl values

    const float* kc = g_k + ((long)(b*C + 8*h + cl))*NPIX;
    const float* vb = g_v + ((long)(b*C + 8*h))*NPIX;

    float acc[9][8];
    float accs[9];
    #pragma unroll
    for (int p = 0; p < 9; p++) {
        accs[p] = 0.0f;
        #pragma unroll
        for (int e = 0; e < 8; e++) acc[p][e] = 0.0f;
    }

    int y0 = blockIdx.x * KV_ROWS;
    for (int y = y0; y < y0 + KV_ROWS; y++) {
        #pragma unroll 1
        for (int xi = 0; xi < 8; xi++) {
            int xx0 = lane + 32*xi;
            float vv[8];
            #pragma unroll
            for (int e = 0; e < 8; e++) vv[e] = vb[e*NPIX + y*WW + xx0];
            #pragma unroll
            for (int i = 0; i < 3; i++) {
                int yy = y + i - 1;
                if (yy < 0 || yy >= HH) continue;
                #pragma unroll
                for (int j = 0; j < 3; j++) {
                    int xj = xx0 + j - 1;
                    if (xj < 0 || xj >= WW) continue;
                    float kl = kc[yy*WW + xj];
                    int pp = i*3 + j;
                    accs[pp] += kl;
                    #pragma unroll
                    for (int e = 0; e < 8; e++)
                        acc[pp][e] = fmaf(kl, vv[e], acc[pp][e]);
                }
            }
        }
    }

    // warp-level reduction
    #pragma unroll
    for (int pp = 0; pp < 9; pp++) {
        #pragma unroll
        for (int e = 0; e < 8; e++) {
            float v = acc[pp][e];
            for (int s = 16; s > 0; s >>= 1) v += __shfl_xor_sync(0xffffffffu, v, s);
            acc[pp][e] = v;
        }
        float v = accs[pp];
        for (int s = 16; s > 0; s >>= 1) v += __shfl_xor_sync(0xffffffffu, v, s);
        accs[pp] = v;
    }

    if (lane == 0) {
        float* out = g_kv + bh*KVSZ;
        #pragma unroll
        for (int pp = 0; pp < 9; pp++) {
            int d = cl*9 + pp;
            #pragma unroll
            for (int e = 0; e < 8; e++) atomicAdd(&out[d*8 + e], acc[pp][e]);
            atomicAdd(&out[576 + d], accs[pp]);
        }
    }
}

// ---------------------------------------------------------------
// per-pixel attention output:
//   num[e] = sum_d q_unfold[d] * kv[d,e] ; den = sum_d q_unfold[d]*ksum[d] + eps
//   o[8h+e] = num[e]/den
// kv matrices for this image in smem (broadcast reads).
// ---------------------------------------------------------------
__global__ __launch_bounds__(256)
void attn_kernel() {
    int b = blockIdx.x >> 8;                          // 256 blocks per image
    int n = ((blockIdx.x & 255) << 8) + threadIdx.x;  // pixel within image
    __shared__ float kvs[HEADS*KVSZ];                 // 5184 floats = 20.7 KB
    for (int i = threadIdx.x; i < HEADS*KVSZ; i += 256)
        kvs[i] = g_kv[b*HEADS*KVSZ + i];
    __syncthreads();

    int y = n >> 8, x = n & 255;
    const float* qb = g_q + (long)b*C*NPIX;

    #pragma unroll 1
    for (int h = 0; h < HEADS; h++) {
        float num[8] = {0,0,0,0,0,0,0,0};
        float den = 0.0f;
        const float* kvh = kvs + h*KVSZ;
        #pragma unroll 1
        for (int cl = 0; cl < 8; cl++) {
            const float* qc = qb + (long)(8*h + cl)*NPIX;
            #pragma unroll
            for (int i = 0; i < 3; i++) {
                int yy = y + i - 1;
                if (yy < 0 || yy >= HH) continue;
                #pragma unroll
                for (int j = 0; j < 3; j++) {
                    int xj = x + j - 1;
                    if (xj < 0 || xj >= WW) continue;
                    float qv = qc[yy*WW + xj];
                    int d = cl*9 + i*3 + j;
                    den = fmaf(qv, kvh[576 + d], den);
                    #pragma unroll
                    for (int e = 0; e < 8; e++)
                        num[e] = fmaf(qv, kvh[d*8 + e], num[e]);
                }
            }
        }
        float inv = 1.0f / (den + 1e-6f);
        long ob = (long)(b*C + 8*h)*NPIX + n;
        #pragma unroll
        for (int e = 0; e < 8; e++)
            g_o[ob + (long)e*NPIX] = num[e] * inv;
    }
}

// ---------------------------------------------------------------
// 3x3 conv (64 -> 64, pad 1) + bias + residual -> out
// tile 32x8 pixels, ic chunks of 8 staged through smem (29.3 KB),
// each thread owns one pixel x all 64 output channels.
// ---------------------------------------------------------------
#define CONV_TX 32
#define CONV_TY 8
#define ICCHUNK 8
__global__ __launch_bounds__(256)
void conv3x3_res_kernel(const float* __restrict__ in,
                        const float* __restrict__ w,
                        const float* __restrict__ bias,
                        const float* __restrict__ res,
                        float* __restrict__ out) {
    int b  = blockIdx.z;
    int x0 = blockIdx.x * CONV_TX;
    int y0 = blockIdx.y * CONV_TY;
    int tx = threadIdx.x & 31;
    int ty = threadIdx.x >> 5;

    __shared__ float xs[ICCHUNK][CONV_TY+2][CONV_TX+2];  // 8*10*34*4 = 10,880 B
    __shared__ float ws[ICCHUNK][9][C];                  // 8*9*64*4  = 18,432 B

    float acc[C];
    #pragma unroll
    for (int oc = 0; oc < C; oc++) acc[oc] = 0.0f;

    const float* inb = in + (long)b*C*NPIX;

    for (int ic0 = 0; ic0 < C; ic0 += ICCHUNK) {
        __syncthreads();
        // input tile (with halo, zero-padded)
        for (int idx = threadIdx.x; idx < ICCHUNK*10*34; idx += 256) {
            int ic = idx / (10*34);
            int r  = idx % (10*34);
            int yy = r / 34, xx = r % 34;
            int gy = y0 + yy - 1, gx = x0 + xx - 1;
            float v = 0.0f;
            if (gy >= 0 && gy < HH && gx >= 0 && gx < WW)
                v = inb[(long)(ic0+ic)*NPIX + gy*WW + gx];
            xs[ic][yy][xx] = v;
        }
        // weights transposed to [ic][pp][oc] for vectorized broadcast reads
        for (int idx = threadIdx.x; idx < ICCHUNK*9*C; idx += 256) {
            int ic = idx / (9*C);
            int r  = idx % (9*C);
            int pp = r / C, oc = r % C;
            ws[ic][pp][oc] = w[(long)oc*(C*9) + (ic0+ic)*9 + pp];
        }
        __syncthreads();

        #pragma unroll 1
        for (int ic = 0; ic < ICCHUNK; ic++) {
            #pragma unroll
            for (int i = 0; i < 3; i++) {
                #pragma unroll
                for (int j = 0; j < 3; j++) {
                    float xv = xs[ic][ty+i][tx+j];
                    const float* wr = ws[ic][i*3+j];
                    #pragma unroll
                    for (int oc = 0; oc < C; oc++)
                        acc[oc] = fmaf(xv, wr[oc], acc[oc]);
                }
            }
        }
    }

    int gy = y0 + ty, gx = x0 + tx;
    long pbase = (long)b*C*NPIX + gy*WW + gx;
    #pragma unroll
    for (int oc = 0; oc < C; oc++)
        out[pbase + (long)oc*NPIX] = acc[oc] + bias[oc] + res[pbase + (long)oc*NPIX];
}

// ---------------------------------------------------------------
// 1x1 conv (64 -> 64) + bias + exact GELU
// ---------------------------------------------------------------
__global__ __launch_bounds__(256)
void pw_gelu_kernel(const float* __restrict__ in,
                    const float* __restrict__ w,
                    const float* __restrict__ bias,
                    float* __restrict__ out) {
    __shared__ float ws[C*C];     // 16 KB
    __shared__ float bs[C];
    for (int i = threadIdx.x; i < C*C; i += 256) ws[i] = w[i];
    if (threadIdx.x < C) bs[threadIdx.x] = bias[threadIdx.x];
    __syncthreads();

    int pix = blockIdx.x * 256 + threadIdx.x;
    int b   = pix >> 16;
    int n   = pix & (NPIX - 1);
    const float* ib = in + (long)b*C*NPIX + n;
    float xv[C];
    #pragma unroll
    for (int c = 0; c < C; c++) xv[c] = ib[(long)c*NPIX];
    long obase = (long)b*C*NPIX + n;
    #pragma unroll 1
    for (int oc = 0; oc < C; oc++) {
        float a = bs[oc];
        const float* wr = ws + oc*C;
        #pragma unroll
        for (int c2 = 0; c2 < C; c2++) a = fmaf(wr[c2], xv[c2], a);
        out[obase + (long)oc*NPIX] = gelu_exact(a);
    }
}

// ---------------------------------------------------------------
// 1x1 conv (64 -> 64) + bias + residual (final output)
// ---------------------------------------------------------------
__global__ __launch_bounds__(256)
void pw_res_kernel(const float* __restrict__ in,
                   const float* __restrict__ w,
                   const float* __restrict__ bias,
                   const float* __restrict__ res,
                   float* __restrict__ out) {
    __shared__ float ws[C*C];     // 16 KB
    __shared__ float bs[C];
    for (int i = threadIdx.x; i < C*C; i += 256) ws[i] = w[i];
    if (threadIdx.x < C) bs[threadIdx.x] = bias[threadIdx.x];
    __syncthreads();

    int pix = blockIdx.x * 256 + threadIdx.x;
    int b   = pix >> 16;
    int n   = pix & (NPIX - 1);
    const float* ib = in + (long)b*C*NPIX + n;
    float xv[C];
    #pragma unroll
    for (int c = 0; c < C; c++) xv[c] = ib[(long)c*NPIX];
    long obase = (long)b*C*NPIX + n;
    #pragma unroll 1
    for (int oc = 0; oc < C; oc++) {
        float a = bs[oc];
        const float* wr = ws + oc*C;
        #pragma unroll
        for (int c2 = 0; c2 < C; c2++) a = fmaf(wr[c2], xv[c2], a);
        out[obase + (long)oc*NPIX] = a + res[obase + (long)oc*NPIX];
    }
}

// ---------------------------------------------------------------
// depthwise 3x3 conv (pad 1) + bias + exact GELU
// ---------------------------------------------------------------
__global__ __launch_bounds__(256)
void dw_gelu_kernel(const float* __restrict__ in,
                    const float* __restrict__ w,
                    const float* __restrict__ bias,
                    float* __restrict__ out) {
    int idx = blockIdx.x * 256 + threadIdx.x;     // (b*C + c)*NPIX + y*W + x
    int x  = idx & 255;
    int y  = (idx >> 8) & 255;
    int bc = idx >> 16;
    int c  = bc & (C - 1);
    const float* ib = in + (long)bc*NPIX;
    float a = bias[c];
    #pragma unroll
    for (int i = 0; i < 3; i++) {
        int yy = y + i - 1;
        if (yy < 0 || yy >= HH) continue;
        #pragma unroll
        for (int j = 0; j < 3; j++) {
            int xj = x + j - 1;
            if (xj < 0 || xj >= WW) continue;
            a = fmaf(w[c*9 + i*3 + j], ib[yy*WW + xj], a);
        }
    }
    out[(long)idx] = gelu_exact(a);
}

// ---------------------------------------------------------------
extern "C" void kernel_launch(void* const* d_in, const int* in_sizes, int n_in,
                              void* d_out, int out_size) {
    const float* x      = (const float*)d_in[0];
    const float* qkv_w  = (const float*)d_in[1];
    const float* qkv_b  = (const float*)d_in[2];
    const float* proj_w = (const float*)d_in[3];
    const float* proj_b = (const float*)d_in[4];
    const float* ffn1_w = (const float*)d_in[5];
    const float* ffn1_b = (const float*)d_in[6];
    const float* dw_w   = (const float*)d_in[7];
    const float* dw_b   = (const float*)d_in[8];
    const float* ffn2_w = (const float*)d_in[9];
    const float* ffn2_b = (const float*)d_in[10];
    float* out = (float*)d_out;

    float *p_o, *p_x1, *p_h1, *p_h2;
    cudaGetSymbolAddress((void**)&p_o,  g_o);
    cudaGetSymbolAddress((void**)&p_x1, g_x1);
    cudaGetSymbolAddress((void**)&p_h1, g_h1);
    cudaGetSymbolAddress((void**)&p_h2, g_h2);

    const int PIX_BLOCKS = BATCH*NPIX/256;     // 512

    zero_kv_kernel<<<(BATCH*HEADS*KVSZ + 255)/256, 256>>>();
    qkv_kernel<<<PIX_BLOCKS, 256>>>(x, qkv_w, qkv_b);
    kv_kernel<<<dim3(HH/KV_ROWS, BATCH*HEADS), 256>>>();
    attn_kernel<<<PIX_BLOCKS, 256>>>();
    conv3x3_res_kernel<<<dim3(WW/CONV_TX, HH/CONV_TY, BATCH), 256>>>(
        p_o, proj_w, proj_b, x, p_x1);                       // x1 = x + proj(o)
    pw_gelu_kernel<<<PIX_BLOCKS, 256>>>(p_x1, ffn1_w, ffn1_b, p_h1);
    dw_gelu_kernel<<<BATCH*C*NPIX/256, 256>>>(p_h1, dw_w, dw_b, p_h2);
    pw_res_kernel<<<PIX_BLOCKS, 256>>>(p_h2, ffn2_w, ffn2_b, p_x1, out);
}

// round 5
// speedup vs baseline: 1.1162x; 1.1162x over previous
#include <cuda_runtime.h>
#include <math.h>
#include <stdint.h>

#define C        64
#define HH       256
#define WW       256
#define NPIX     65536            // HH*WW
#define BATCH    2
#define HEADS    8
#define KVSZ     648              // 72*8 + 72 per (b,h)

// -------- scratch (device globals: allocation-free at launch time) --------
__device__ float g_q [BATCH*C*NPIX];
__device__ float g_k [BATCH*C*NPIX];
__device__ float g_v [BATCH*C*NPIX];
__device__ float g_o [BATCH*C*NPIX];
__device__ float g_x1[BATCH*C*NPIX];
__device__ float g_h1[BATCH*C*NPIX];
__device__ float g_h2[BATCH*C*NPIX];
__device__ float g_kv[BATCH*HEADS*KVSZ];

__device__ __forceinline__ float gelu_exact(float v) {
    return 0.5f * v * (1.0f + erff(v * 0.7071067811865476f));
}

__device__ __forceinline__ float to_tf32(float x) {
    uint32_t u;
    asm("cvt.rna.tf32.f32 %0, %1;" : "=r"(u) : "f"(x));
    return __uint_as_float(u);
}

__device__ __forceinline__ void mma_tf32(float* c,
        uint32_t a0, uint32_t a1, uint32_t a2, uint32_t a3,
        uint32_t b0, uint32_t b1) {
    asm volatile(
        "mma.sync.aligned.m16n8k8.row.col.f32.tf32.tf32.f32 "
        "{%0,%1,%2,%3}, {%4,%5,%6,%7}, {%8,%9}, {%0,%1,%2,%3};\n"
        : "+f"(c[0]), "+f"(c[1]), "+f"(c[2]), "+f"(c[3])
        : "r"(a0), "r"(a1), "r"(a2), "r"(a3), "r"(b0), "r"(b1));
}

// ---------------------------------------------------------------
// zero the kv accumulator
// ---------------------------------------------------------------
__global__ void zero_kv_kernel() {
    int i = blockIdx.x * blockDim.x + threadIdx.x;
    if (i < BATCH*HEADS*KVSZ) g_kv[i] = 0.0f;
}

// ---------------------------------------------------------------
// Unified tensor-core conv kernel (tf32 mma.sync m16n8k8).
//   out[oc][pix] = act( sum_{ic,pp} w * in[ic][pix + off(pp)] + bias[oc] ) [+ res]
// KH = 1 (pointwise) or 3 (3x3, pad 1).
// MODE: 0 = none, 1 = relu, 2 = gelu, 3 = add residual.
// Block: 256 threads = 8 warps; each block = 128 contiguous pixels of one
// row (x-tile of 128), all 64 output channels. Warp w owns pixels
// [w*16, w*16+16). K staged in ic-chunks of 8 through smem (tf32-rounded).
// ---------------------------------------------------------------
template<int KH, int MODE>
__global__ __launch_bounds__(256)
void mma_conv_kernel(const float* __restrict__ in,
                     const float* __restrict__ w,
                     const float* __restrict__ bias,
                     const float* __restrict__ res,
                     float* __restrict__ out) {
    __shared__ float xs[8][KH][130];        // input tile (halo for KH=3), padded rows
    __shared__ float ws[KH*KH][8][66];      // weights [pp][ic][oc], padded
    __shared__ float bs[C];

    int b   = blockIdx.y;
    int y   = blockIdx.x >> 1;
    int x0  = (blockIdx.x & 1) << 7;        // 0 or 128
    int tid = threadIdx.x;
    int wid = tid >> 5;
    int lane = tid & 31;

    const float* inb = in + (size_t)b*C*NPIX;
    if (tid < C) bs[tid] = bias[tid];

    float acc[8][4];
    #pragma unroll
    for (int n = 0; n < 8; n++)
        #pragma unroll
        for (int j = 0; j < 4; j++) acc[n][j] = 0.0f;

    int pxA = (wid << 4) + (lane >> 2);     // local pixel for a0/a2
    int icA = lane & 3;
    int ocB = lane >> 2;

    for (int ic0 = 0; ic0 < C; ic0 += 8) {
        __syncthreads();
        // ---- fill input tile ----
        const int XEL = 8*KH*130;
        for (int idx = tid; idx < XEL; idx += 256) {
            int ic = idx / (KH*130);
            int r  = idx % (KH*130);
            int dy = r / 130;
            int xx = r % 130;
            float v = 0.0f;
            if (KH == 3) {
                int gy = y + dy - 1;
                int gx = x0 + xx - 1;
                if (gy >= 0 && gy < HH && (unsigned)gx < WW)
                    v = inb[(size_t)(ic0+ic)*NPIX + gy*WW + gx];
            } else {
                if (xx < 128)
                    v = inb[(size_t)(ic0+ic)*NPIX + y*WW + x0 + xx];
            }
            xs[ic][dy][xx] = to_tf32(v);
        }
        // ---- fill weights [pp][ic][oc] ----
        const int WEL = KH*KH*8*64;
        for (int idx = tid; idx < WEL; idx += 256) {
            int pp = idx >> 9;              // / 512
            int ic = (idx >> 6) & 7;
            int oc = idx & 63;
            float v = (KH == 3)
                ? w[(size_t)oc*(C*9) + (size_t)(ic0+ic)*9 + pp]
                : w[(size_t)oc*C + (ic0+ic)];
            ws[pp][ic][oc] = to_tf32(v);
        }
        __syncthreads();

        #pragma unroll
        for (int pp = 0; pp < KH*KH; pp++) {
            int dy = pp / KH, dx = pp % KH;
            uint32_t a0 = __float_as_uint(xs[icA  ][dy][pxA + dx]);
            uint32_t a1 = __float_as_uint(xs[icA  ][dy][pxA + 8 + dx]);
            uint32_t a2 = __float_as_uint(xs[icA+4][dy][pxA + dx]);
            uint32_t a3 = __float_as_uint(xs[icA+4][dy][pxA + 8 + dx]);
            #pragma unroll
            for (int n = 0; n < 8; n++) {
                uint32_t b0 = __float_as_uint(ws[pp][icA  ][(n<<3) + ocB]);
                uint32_t b1 = __float_as_uint(ws[pp][icA+4][(n<<3) + ocB]);
                mma_tf32(acc[n], a0, a1, a2, a3, b0, b1);
            }
        }
    }

    // ---- epilogue: bias + activation (+ residual), store CHW ----
    int pixbase = y*WW + x0 + (wid << 4) + (lane >> 2);
    size_t obase = (size_t)b*C*NPIX;
    #pragma unroll
    for (int n = 0; n < 8; n++) {
        int oc = (n << 3) + ((lane & 3) << 1);
        #pragma unroll
        for (int half = 0; half < 2; half++) {
            float v0 = acc[n][half*2 + 0] + bs[oc];
            float v1 = acc[n][half*2 + 1] + bs[oc+1];
            int px = pixbase + half*8;
            size_t i0 = obase + (size_t)oc*NPIX + px;
            size_t i1 = i0 + NPIX;
            if (MODE == 1) { v0 = fmaxf(v0, 0.0f); v1 = fmaxf(v1, 0.0f); }
            else if (MODE == 2) { v0 = gelu_exact(v0); v1 = gelu_exact(v1); }
            else if (MODE == 3) { v0 += res[i0]; v1 += res[i1]; }
            out[i0] = v0;
            out[i1] = v1;
        }
    }
}

// ---------------------------------------------------------------
// kv[b,h,d,e] = sum_n k_unfold[d,n] * v[e,n]  ;  ksum[b,h,d] = sum_n k_unfold[d,n]
// ---------------------------------------------------------------
#define KV_ROWS 16
__global__ __launch_bounds__(256)
void kv_kernel() {
    int bh = blockIdx.y;                  // 0..15
    int b  = bh >> 3;
    int h  = bh & 7;
    int warp = threadIdx.x >> 5;
    int lane = threadIdx.x & 31;
    int cl = warp;

    const float* kc = g_k + ((long)(b*C + 8*h + cl))*NPIX;
    const float* vb = g_v + ((long)(b*C + 8*h))*NPIX;

    float acc[9][8];
    float accs[9];
    #pragma unroll
    for (int p = 0; p < 9; p++) {
        accs[p] = 0.0f;
        #pragma unroll
        for (int e = 0; e < 8; e++) acc[p][e] = 0.0f;
    }

    int y0 = blockIdx.x * KV_ROWS;
    for (int y = y0; y < y0 + KV_ROWS; y++) {
        #pragma unroll 1
        for (int xi = 0; xi < 8; xi++) {
            int xx0 = lane + 32*xi;
            float vv[8];
            #pragma unroll
            for (int e = 0; e < 8; e++) vv[e] = vb[e*NPIX + y*WW + xx0];
            #pragma unroll
            for (int i = 0; i < 3; i++) {
                int yy = y + i - 1;
                if (yy < 0 || yy >= HH) continue;
                #pragma unroll
                for (int j = 0; j < 3; j++) {
                    int xj = xx0 + j - 1;
                    if (xj < 0 || xj >= WW) continue;
                    float kl = kc[yy*WW + xj];
                    int pp = i*3 + j;
                    accs[pp] += kl;
                    #pragma unroll
                    for (int e = 0; e < 8; e++)
                        acc[pp][e] = fmaf(kl, vv[e], acc[pp][e]);
                }
            }
        }
    }

    #pragma unroll
    for (int pp = 0; pp < 9; pp++) {
        #pragma unroll
        for (int e = 0; e < 8; e++) {
            float v = acc[pp][e];
            for (int s = 16; s > 0; s >>= 1) v += __shfl_xor_sync(0xffffffffu, v, s);
            acc[pp][e] = v;
        }
        float v = accs[pp];
        for (int s = 16; s > 0; s >>= 1) v += __shfl_xor_sync(0xffffffffu, v, s);
        accs[pp] = v;
    }

    if (lane == 0) {
        float* out = g_kv + bh*KVSZ;
        #pragma unroll
        for (int pp = 0; pp < 9; pp++) {
            int d = cl*9 + pp;
            #pragma unroll
            for (int e = 0; e < 8; e++) atomicAdd(&out[d*8 + e], acc[pp][e]);
            atomicAdd(&out[576 + d], accs[pp]);
        }
    }
}

// ---------------------------------------------------------------
// per-pixel attention output
// ---------------------------------------------------------------
__global__ __launch_bounds__(256)
void attn_kernel() {
    int b = blockIdx.x >> 8;
    int n = ((blockIdx.x & 255) << 8) + threadIdx.x;
    __shared__ float kvs[HEADS*KVSZ];
    for (int i = threadIdx.x; i < HEADS*KVSZ; i += 256)
        kvs[i] = g_kv[b*HEADS*KVSZ + i];
    __syncthreads();

    int y = n >> 8, x = n & 255;
    const float* qb = g_q + (long)b*C*NPIX;

    #pragma unroll 1
    for (int h = 0; h < HEADS; h++) {
        float num[8] = {0,0,0,0,0,0,0,0};
        float den = 0.0f;
        const float* kvh = kvs + h*KVSZ;
        #pragma unroll 1
        for (int cl = 0; cl < 8; cl++) {
            const float* qc = qb + (long)(8*h + cl)*NPIX;
            #pragma unroll
            for (int i = 0; i < 3; i++) {
                int yy = y + i - 1;
                if (yy < 0 || yy >= HH) continue;
                #pragma unroll
                for (int j = 0; j < 3; j++) {
                    int xj = x + j - 1;
                    if (xj < 0 || xj >= WW) continue;
                    float qv = qc[yy*WW + xj];
                    int d = cl*9 + i*3 + j;
                    den = fmaf(qv, kvh[576 + d], den);
                    #pragma unroll
                    for (int e = 0; e < 8; e++)
                        num[e] = fmaf(qv, kvh[d*8 + e], num[e]);
                }
            }
        }
        float inv = 1.0f / (den + 1e-6f);
        long ob = (long)(b*C + 8*h)*NPIX + n;
        #pragma unroll
        for (int e = 0; e < 8; e++)
            g_o[ob + (long)e*NPIX] = num[e] * inv;
    }
}

// ---------------------------------------------------------------
// depthwise 3x3 conv (pad 1) + bias + exact GELU
// ---------------------------------------------------------------
__global__ __launch_bounds__(256)
void dw_gelu_kernel(const float* __restrict__ in,
                    const float* __restrict__ w,
                    const float* __restrict__ bias,
                    float* __restrict__ out) {
    int idx = blockIdx.x * 256 + threadIdx.x;
    int x  = idx & 255;
    int y  = (idx >> 8) & 255;
    int bc = idx >> 16;
    int c  = bc & (C - 1);
    const float* ib = in + (long)bc*NPIX;
    float a = bias[c];
    #pragma unroll
    for (int i = 0; i < 3; i++) {
        int yy = y + i - 1;
        if (yy < 0 || yy >= HH) continue;
        #pragma unroll
        for (int j = 0; j < 3; j++) {
            int xj = x + j - 1;
            if (xj < 0 || xj >= WW) continue;
            a = fmaf(w[c*9 + i*3 + j], ib[yy*WW + xj], a);
        }
    }
    out[(long)idx] = gelu_exact(a);
}

// ---------------------------------------------------------------
extern "C" void kernel_launch(void* const* d_in, const int* in_sizes, int n_in,
                              void* d_out, int out_size) {
    const float* x      = (const float*)d_in[0];
    const float* qkv_w  = (const float*)d_in[1];
    const float* qkv_b  = (const float*)d_in[2];
    const float* proj_w = (const float*)d_in[3];
    const float* proj_b = (const float*)d_in[4];
    const float* ffn1_w = (const float*)d_in[5];
    const float* ffn1_b = (const float*)d_in[6];
    const float* dw_w   = (const float*)d_in[7];
    const float* dw_b   = (const float*)d_in[8];
    const float* ffn2_w = (const float*)d_in[9];
    const float* ffn2_b = (const float*)d_in[10];
    float* out = (float*)d_out;

    float *p_q, *p_k, *p_v, *p_o, *p_x1, *p_h1, *p_h2;
    cudaGetSymbolAddress((void**)&p_q,  g_q);
    cudaGetSymbolAddress((void**)&p_k,  g_k);
    cudaGetSymbolAddress((void**)&p_v,  g_v);
    cudaGetSymbolAddress((void**)&p_o,  g_o);
    cudaGetSymbolAddress((void**)&p_x1, g_x1);
    cudaGetSymbolAddress((void**)&p_h1, g_h1);
    cudaGetSymbolAddress((void**)&p_h2, g_h2);

    dim3 gconv(HH*2, BATCH);    // 128-pixel x-tiles: 2 per row * 256 rows

    zero_kv_kernel<<<(BATCH*HEADS*KVSZ + 255)/256, 256>>>();
    // qkv: 3 tensor-core pointwise GEMMs (q,k relu; v plain)
    mma_conv_kernel<1,1><<<gconv, 256>>>(x, qkv_w,            qkv_b,       nullptr, p_q);
    mma_conv_kernel<1,1><<<gconv, 256>>>(x, qkv_w + C*C,      qkv_b + C,   nullptr, p_k);
    mma_conv_kernel<1,0><<<gconv, 256>>>(x, qkv_w + 2*C*C,    qkv_b + 2*C, nullptr, p_v);
    kv_kernel<<<dim3(HH/KV_ROWS, BATCH*HEADS), 256>>>();
    attn_kernel<<<BATCH*NPIX/256, 256>>>();
    // proj 3x3 + residual(x) -> x1
    mma_conv_kernel<3,3><<<gconv, 256>>>(p_o, proj_w, proj_b, x, p_x1);
    // ffn1 1x1 + gelu -> h1
    mma_conv_kernel<1,2><<<gconv, 256>>>(p_x1, ffn1_w, ffn1_b, nullptr, p_h1);
    dw_gelu_kernel<<<BATCH*C*NPIX/256, 256>>>(p_h1, dw_w, dw_b, p_h2);
    // ffn2 1x1 + residual(x1) -> out
    mma_conv_kernel<1,3><<<gconv, 256>>>(p_h2, ffn2_w, ffn2_b, p_x1, out);
}

// round 6
// speedup vs baseline: 1.7928x; 1.6061x over previous
#include <cuda_runtime.h>
#include <math.h>
#include <stdint.h>

#define C        64
#define HH       256
#define WW       256
#define NPIX     65536            // HH*WW
#define BATCH    2
#define HEADS    8
#define KVSZ     648              // 72*8 + 72 per (b,h)

// -------- scratch (device globals: allocation-free at launch time) --------
__device__ float g_q [BATCH*C*NPIX];
__device__ float g_k [BATCH*C*NPIX];
__device__ float g_v [BATCH*C*NPIX];
__device__ float g_o [BATCH*C*NPIX];
__device__ float g_x1[BATCH*C*NPIX];
__device__ float g_h1[BATCH*C*NPIX];
__device__ float g_h2[BATCH*C*NPIX];
__device__ float g_kv[BATCH*HEADS*KVSZ];

__device__ __forceinline__ float gelu_exact(float v) {
    return 0.5f * v * (1.0f + erff(v * 0.7071067811865476f));
}

__device__ __forceinline__ float to_tf32(float x) {
    uint32_t u;
    asm("cvt.rna.tf32.f32 %0, %1;" : "=r"(u) : "f"(x));
    return __uint_as_float(u);
}
__device__ __forceinline__ uint32_t to_tf32_u(float x) {
    uint32_t u;
    asm("cvt.rna.tf32.f32 %0, %1;" : "=r"(u) : "f"(x));
    return u;
}

// A = 16(oc) x 8(k), row-major; B = 8(k) x 8(px), col-major; C = 16 x 8
// a0:(m=g,k=l4) a1:(m=g+8,k=l4) a2:(m=g,k=l4+4) a3:(m=g+8,k=l4+4)
// b0:(k=l4,n=g) b1:(k=l4+4,n=g)
// c0:(m=g,n=2*l4) c1:(g,2*l4+1) c2:(g+8,2*l4) c3:(g+8,2*l4+1)
__device__ __forceinline__ void mma_tf32(float* c,
        uint32_t a0, uint32_t a1, uint32_t a2, uint32_t a3,
        uint32_t b0, uint32_t b1) {
    asm volatile(
        "mma.sync.aligned.m16n8k8.row.col.f32.tf32.tf32.f32 "
        "{%0,%1,%2,%3}, {%4,%5,%6,%7}, {%8,%9}, {%0,%1,%2,%3};\n"
        : "+f"(c[0]), "+f"(c[1]), "+f"(c[2]), "+f"(c[3])
        : "r"(a0), "r"(a1), "r"(a2), "r"(a3), "r"(b0), "r"(b1));
}

// ---------------------------------------------------------------
__global__ void zero_kv_kernel() {
    int i = blockIdx.x * blockDim.x + threadIdx.x;
    if (i < BATCH*HEADS*KVSZ) g_kv[i] = 0.0f;
}

// ---------------------------------------------------------------
// Fused qkv pointwise GEMM: out{q,k,v}[oc][px] = act(W[oc][:]·x[:][px] + b)
// Block: 256 thr = 8 warps, 128 contiguous pixels, all 192 oc.
// x tile in smem (one fill, one barrier); weights in registers (A operand).
// ---------------------------------------------------------------
__global__ __launch_bounds__(256)
void pw_qkv_kernel(const float* __restrict__ x,
                   const float* __restrict__ w,
                   const float* __restrict__ bias) {
    __shared__ float xs[C][136];            // 34.8 KB, pad 136 -> conflict-free

    int b    = blockIdx.y;
    int pix0 = blockIdx.x * 128;
    int tid  = threadIdx.x;
    const float* inb = x + (size_t)b*C*NPIX + pix0;

    // fill: 64 ic x 32 float4
    #pragma unroll
    for (int it = 0; it < 8; it++) {
        int idx = tid + it*256;
        int ic = idx >> 5, p4 = (idx & 31) << 2;
        float4 v = *(const float4*)(inb + (size_t)ic*NPIX + p4);
        v.x = to_tf32(v.x); v.y = to_tf32(v.y);
        v.z = to_tf32(v.z); v.w = to_tf32(v.w);
        *(float4*)&xs[ic][p4] = v;
    }
    __syncthreads();

    int lane = tid & 31, wid = tid >> 5;
    int g = lane >> 2, l4 = lane & 3;
    int oc0 = (wid & 3) * 16;
    int pxw = (wid >> 2) * 64;

    #pragma unroll
    for (int p = 0; p < 3; p++) {
        float* op = ((p == 0) ? g_q : (p == 1) ? g_k : g_v) + (size_t)b*C*NPIX + pix0;
        // hoist weights (A frags) for this part: 8 ksteps x 4 regs
        uint32_t Ar[8][4];
        const float* wp = w + (size_t)(p*C + oc0 + g)*C + l4;
        #pragma unroll
        for (int ks = 0; ks < 8; ks++) {
            Ar[ks][0] = to_tf32_u(wp[ks*8]);
            Ar[ks][1] = to_tf32_u(wp[8*C + ks*8]);
            Ar[ks][2] = to_tf32_u(wp[ks*8 + 4]);
            Ar[ks][3] = to_tf32_u(wp[8*C + ks*8 + 4]);
        }
        float b_lo = bias[p*C + oc0 + g];
        float b_hi = bias[p*C + oc0 + g + 8];

        #pragma unroll
        for (int f = 0; f < 8; f++) {
            int px0f = pxw + f*8;
            float acc[4] = {0.f, 0.f, 0.f, 0.f};
            #pragma unroll
            for (int ks = 0; ks < 8; ks++) {
                uint32_t b0 = __float_as_uint(xs[ks*8 + l4    ][px0f + g]);
                uint32_t b1 = __float_as_uint(xs[ks*8 + 4 + l4][px0f + g]);
                mma_tf32(acc, Ar[ks][0], Ar[ks][1], Ar[ks][2], Ar[ks][3], b0, b1);
            }
            float v0 = acc[0] + b_lo, v1 = acc[1] + b_lo;
            float v2 = acc[2] + b_hi, v3 = acc[3] + b_hi;
            if (p < 2) {
                v0 = fmaxf(v0, 0.f); v1 = fmaxf(v1, 0.f);
                v2 = fmaxf(v2, 0.f); v3 = fmaxf(v3, 0.f);
            }
            size_t olo = (size_t)(oc0 + g)*NPIX + px0f + 2*l4;
            *(float2*)&op[olo]          = make_float2(v0, v1);
            *(float2*)&op[olo + 8*NPIX] = make_float2(v2, v3);
        }
    }
}

// ---------------------------------------------------------------
// Single pointwise GEMM 64->64. MODE: 2 = gelu, 3 = +res.
// ---------------------------------------------------------------
template<int MODE>
__global__ __launch_bounds__(256)
void pw_single_kernel(const float* __restrict__ in,
                      const float* __restrict__ w,
                      const float* __restrict__ bias,
                      const float* __restrict__ res,
                      float* __restrict__ out) {
    __shared__ float xs[C][136];

    int b    = blockIdx.y;
    int pix0 = blockIdx.x * 128;
    int tid  = threadIdx.x;
    const float* inb = in + (size_t)b*C*NPIX + pix0;

    #pragma unroll
    for (int it = 0; it < 8; it++) {
        int idx = tid + it*256;
        int ic = idx >> 5, p4 = (idx & 31) << 2;
        float4 v = *(const float4*)(inb + (size_t)ic*NPIX + p4);
        v.x = to_tf32(v.x); v.y = to_tf32(v.y);
        v.z = to_tf32(v.z); v.w = to_tf32(v.w);
        *(float4*)&xs[ic][p4] = v;
    }
    __syncthreads();

    int lane = tid & 31, wid = tid >> 5;
    int g = lane >> 2, l4 = lane & 3;
    int oc0 = (wid & 3) * 16;
    int pxw = (wid >> 2) * 64;

    uint32_t Ar[8][4];
    const float* wp = w + (size_t)(oc0 + g)*C + l4;
    #pragma unroll
    for (int ks = 0; ks < 8; ks++) {
        Ar[ks][0] = to_tf32_u(wp[ks*8]);
        Ar[ks][1] = to_tf32_u(wp[8*C + ks*8]);
        Ar[ks][2] = to_tf32_u(wp[ks*8 + 4]);
        Ar[ks][3] = to_tf32_u(wp[8*C + ks*8 + 4]);
    }
    float b_lo = bias[oc0 + g];
    float b_hi = bias[oc0 + g + 8];
    float* op = out + (size_t)b*C*NPIX + pix0;
    const float* rp = (MODE == 3) ? res + (size_t)b*C*NPIX + pix0 : nullptr;

    #pragma unroll
    for (int f = 0; f < 8; f++) {
        int px0f = pxw + f*8;
        float acc[4] = {0.f, 0.f, 0.f, 0.f};
        #pragma unroll
        for (int ks = 0; ks < 8; ks++) {
            uint32_t b0 = __float_as_uint(xs[ks*8 + l4    ][px0f + g]);
            uint32_t b1 = __float_as_uint(xs[ks*8 + 4 + l4][px0f + g]);
            mma_tf32(acc, Ar[ks][0], Ar[ks][1], Ar[ks][2], Ar[ks][3], b0, b1);
        }
        float v0 = acc[0] + b_lo, v1 = acc[1] + b_lo;
        float v2 = acc[2] + b_hi, v3 = acc[3] + b_hi;
        size_t olo = (size_t)(oc0 + g)*NPIX + px0f + 2*l4;
        size_t ohi = olo + 8*NPIX;
        if (MODE == 2) {
            v0 = gelu_exact(v0); v1 = gelu_exact(v1);
            v2 = gelu_exact(v2); v3 = gelu_exact(v3);
        } else {
            v0 += rp[olo]; v1 += rp[olo+1];
            v2 += rp[ohi]; v3 += rp[ohi+1];
        }
        *(float2*)&op[olo] = make_float2(v0, v1);
        *(float2*)&op[ohi] = make_float2(v2, v3);
    }
}

// ---------------------------------------------------------------
// proj 3x3 conv (64->64, pad 1) + bias + residual.
// Block: one row y, 128 px, all 64 oc. ic-chunk 16 in smem with halo;
// weights in registers per (chunk, pp, kstep).
// ---------------------------------------------------------------
__global__ __launch_bounds__(256)
void proj3x3_kernel(const float* __restrict__ in,
                    const float* __restrict__ w,
                    const float* __restrict__ bias,
                    const float* __restrict__ res,
                    float* __restrict__ out) {
    __shared__ float xs[16][3][136];        // 26.1 KB; xx in [0,130): gx = x0 + xx - 1

    int b  = blockIdx.y;
    int y  = blockIdx.x >> 1;
    int x0 = (blockIdx.x & 1) << 7;
    int tid = threadIdx.x;
    int lane = tid & 31, wid = tid >> 5;
    int g = lane >> 2, l4 = lane & 3;
    int oc0 = (wid & 3) * 16;
    int pxw = (wid >> 2) * 64;

    const float* inb = in + (size_t)b*C*NPIX;

    float acc[8][4];
    #pragma unroll
    for (int f = 0; f < 8; f++)
        #pragma unroll
        for (int j = 0; j < 4; j++) acc[f][j] = 0.f;

    for (int ic0 = 0; ic0 < C; ic0 += 16) {
        __syncthreads();
        // interior: 16 ic x 3 dy x 32 float4 -> xs[ic][dy][1 + q4*4 ..]
        #pragma unroll
        for (int it = 0; it < 6; it++) {
            int idx = tid + it*256;
            int ic = idx / 96, r = idx % 96;
            int dy = r >> 5, q4 = (r & 31) << 2;
            int gy = y + dy - 1;
            float4 v = make_float4(0.f, 0.f, 0.f, 0.f);
            if (gy >= 0 && gy < HH)
                v = *(const float4*)(inb + (size_t)(ic0+ic)*NPIX + gy*WW + x0 + q4);
            xs[ic][dy][1 + q4    ] = to_tf32(v.x);
            xs[ic][dy][1 + q4 + 1] = to_tf32(v.y);
            xs[ic][dy][1 + q4 + 2] = to_tf32(v.z);
            xs[ic][dy][1 + q4 + 3] = to_tf32(v.w);
        }
        // halo: 16 ic x 3 dy x 2 sides
        if (tid < 96) {
            int ic = tid / 6, r = tid % 6;
            int dy = r >> 1, side = r & 1;
            int xx = side ? 129 : 0;
            int gy = y + dy - 1;
            int gx = x0 + xx - 1;
            float v = 0.f;
            if (gy >= 0 && gy < HH && (unsigned)gx < WW)
                v = inb[(size_t)(ic0+ic)*NPIX + gy*WW + gx];
            xs[ic][dy][xx] = to_tf32(v);
        }
        __syncthreads();

        #pragma unroll
        for (int pp = 0; pp < 9; pp++) {
            int dy = pp / 3, dx = pp % 3;
            uint32_t Ar[2][4];
            #pragma unroll
            for (int ks = 0; ks < 2; ks++) {
                const float* wp = w + (size_t)(oc0 + g)*(C*9) + (size_t)(ic0 + ks*8 + l4)*9 + pp;
                Ar[ks][0] = to_tf32_u(wp[0]);
                Ar[ks][1] = to_tf32_u(wp[8*C*9]);
                Ar[ks][2] = to_tf32_u(wp[4*9]);
                Ar[ks][3] = to_tf32_u(wp[8*C*9 + 4*9]);
            }
            #pragma unroll
            for (int f = 0; f < 8; f++) {
                int xb = pxw + f*8 + g + dx;     // xs xx index (= local px + dx)
                #pragma unroll
                for (int ks = 0; ks < 2; ks++) {
                    uint32_t b0 = __float_as_uint(xs[ks*8 + l4    ][dy][xb]);
                    uint32_t b1 = __float_as_uint(xs[ks*8 + 4 + l4][dy][xb]);
                    mma_tf32(acc[f], Ar[ks][0], Ar[ks][1], Ar[ks][2], Ar[ks][3], b0, b1);
                }
            }
        }
    }

    float b_lo = bias[oc0 + g];
    float b_hi = bias[oc0 + g + 8];
    size_t pbase = (size_t)b*C*NPIX + (size_t)y*WW + x0;
    #pragma unroll
    for (int f = 0; f < 8; f++) {
        int px = pxw + f*8 + 2*l4;
        size_t olo = pbase + (size_t)(oc0 + g)*NPIX + px;
        size_t ohi = olo + 8*NPIX;
        float v0 = acc[f][0] + b_lo + res[olo];
        float v1 = acc[f][1] + b_lo + res[olo+1];
        float v2 = acc[f][2] + b_hi + res[ohi];
        float v3 = acc[f][3] + b_hi + res[ohi+1];
        *(float2*)&out[olo] = make_float2(v0, v1);
        *(float2*)&out[ohi] = make_float2(v2, v3);
    }
}

// ---------------------------------------------------------------
// kv[b,h,d,e] = sum_n k_unfold[d,n] * v[e,n]  ;  ksum[b,h,d] = sum_n k_unfold[d,n]
// ---------------------------------------------------------------
#define KV_ROWS 16
__global__ __launch_bounds__(256)
void kv_kernel() {
    int bh = blockIdx.y;
    int b  = bh >> 3;
    int h  = bh & 7;
    int warp = threadIdx.x >> 5;
    int lane = threadIdx.x & 31;
    int cl = warp;

    const float* kc = g_k + ((size_t)(b*C + 8*h + cl))*NPIX;
    const float* vb = g_v + ((size_t)(b*C + 8*h))*NPIX;

    float acc[9][8];
    float accs[9];
    #pragma unroll
    for (int p = 0; p < 9; p++) {
        accs[p] = 0.0f;
        #pragma unroll
        for (int e = 0; e < 8; e++) acc[p][e] = 0.0f;
    }

    int y0 = blockIdx.x * KV_ROWS;
    for (int y = y0; y < y0 + KV_ROWS; y++) {
        #pragma unroll 1
        for (int xi = 0; xi < 8; xi++) {
            int xx0 = lane + 32*xi;
            float vv[8];
            #pragma unroll
            for (int e = 0; e < 8; e++) vv[e] = vb[e*NPIX + y*WW + xx0];
            #pragma unroll
            for (int i = 0; i < 3; i++) {
                int yy = y + i - 1;
                if (yy < 0 || yy >= HH) continue;
                #pragma unroll
                for (int j = 0; j < 3; j++) {
                    int xj = xx0 + j - 1;
                    if (xj < 0 || xj >= WW) continue;
                    float kl = kc[yy*WW + xj];
                    int pp = i*3 + j;
                    accs[pp] += kl;
                    #pragma unroll
                    for (int e = 0; e < 8; e++)
                        acc[pp][e] = fmaf(kl, vv[e], acc[pp][e]);
                }
            }
        }
    }

    #pragma unroll
    for (int pp = 0; pp < 9; pp++) {
        #pragma unroll
        for (int e = 0; e < 8; e++) {
            float v = acc[pp][e];
            for (int s = 16; s > 0; s >>= 1) v += __shfl_xor_sync(0xffffffffu, v, s);
            acc[pp][e] = v;
        }
        float v = accs[pp];
        for (int s = 16; s > 0; s >>= 1) v += __shfl_xor_sync(0xffffffffu, v, s);
        accs[pp] = v;
    }

    if (lane == 0) {
        float* outp = g_kv + bh*KVSZ;
        #pragma unroll
        for (int pp = 0; pp < 9; pp++) {
            int d = cl*9 + pp;
            #pragma unroll
            for (int e = 0; e < 8; e++) atomicAdd(&outp[d*8 + e], acc[pp][e]);
            atomicAdd(&outp[576 + d], accs[pp]);
        }
    }
}

// ---------------------------------------------------------------
// per-pixel attention; 4 consecutive pixels per thread.
// ---------------------------------------------------------------
__global__ __launch_bounds__(256)
void attn_kernel() {
    int b    = blockIdx.x >> 6;                 // 64 blocks per image
    int base = (blockIdx.x & 63) * 1024;
    __shared__ float kvs[HEADS*KVSZ];           // 20.7 KB
    for (int i = threadIdx.x; i < HEADS*KVSZ; i += 256)
        kvs[i] = g_kv[b*HEADS*KVSZ + i];
    __syncthreads();

    int n0  = base + threadIdx.x * 4;
    int y   = n0 >> 8;
    int xx0 = n0 & 255;                         // multiple of 4, same row for 4 px
    const float* qb = g_q + (size_t)b*C*NPIX;

    #pragma unroll 1
    for (int h = 0; h < HEADS; h++) {
        float num[4][8];
        float den[4] = {0.f, 0.f, 0.f, 0.f};
        #pragma unroll
        for (int t = 0; t < 4; t++)
            #pragma unroll
            for (int e = 0; e < 8; e++) num[t][e] = 0.f;

        const float* kvh = kvs + h*KVSZ;
        #pragma unroll 1
        for (int cl = 0; cl < 8; cl++) {
            const float* qc = qb + (size_t)(8*h + cl)*NPIX;
            #pragma unroll
            for (int i = 0; i < 3; i++) {
                int yy = y + i - 1;
                if (yy < 0 || yy >= HH) continue;
                const float* qr = qc + yy*WW;
                float qrow[6];
                #pragma unroll
                for (int t = 0; t < 6; t++) {
                    int gx = xx0 - 1 + t;
                    qrow[t] = ((unsigned)gx < WW) ? qr[gx] : 0.f;
                }
                #pragma unroll
                for (int j = 0; j < 3; j++) {
                    int d = cl*9 + i*3 + j;
                    float ks = kvh[576 + d];
                    const float* kvd = kvh + d*8;
                    #pragma unroll
                    for (int t = 0; t < 4; t++) {
                        float qv = qrow[t + j];
                        den[t] = fmaf(qv, ks, den[t]);
                        #pragma unroll
                        for (int e = 0; e < 8; e++)
                            num[t][e] = fmaf(qv, kvd[e], num[t][e]);
                    }
                }
            }
        }
        float inv[4];
        #pragma unroll
        for (int t = 0; t < 4; t++) inv[t] = 1.0f / (den[t] + 1e-6f);
        #pragma unroll
        for (int e = 0; e < 8; e++) {
            float4 v = make_float4(num[0][e]*inv[0], num[1][e]*inv[1],
                                   num[2][e]*inv[2], num[3][e]*inv[3]);
            *(float4*)&g_o[(size_t)(b*C + 8*h + e)*NPIX + n0] = v;
        }
    }
}

// ---------------------------------------------------------------
// depthwise 3x3 conv (pad 1) + bias + exact GELU
// ---------------------------------------------------------------
__global__ __launch_bounds__(256)
void dw_gelu_kernel(const float* __restrict__ in,
                    const float* __restrict__ w,
                    const float* __restrict__ bias,
                    float* __restrict__ out) {
    int idx = blockIdx.x * 256 + threadIdx.x;
    int x  = idx & 255;
    int y  = (idx >> 8) & 255;
    int bc = idx >> 16;
    int c  = bc & (C - 1);
    const float* ib = in + (size_t)bc*NPIX;
    float a = bias[c];
    #pragma unroll
    for (int i = 0; i < 3; i++) {
        int yy = y + i - 1;
        if (yy < 0 || yy >= HH) continue;
        #pragma unroll
        for (int j = 0; j < 3; j++) {
            int xj = x + j - 1;
            if (xj < 0 || xj >= WW) continue;
            a = fmaf(w[c*9 + i*3 + j], ib[yy*WW + xj], a);
        }
    }
    out[(size_t)idx] = gelu_exact(a);
}

// ---------------------------------------------------------------
extern "C" void kernel_launch(void* const* d_in, const int* in_sizes, int n_in,
                              void* d_out, int out_size) {
    const float* x      = (const float*)d_in[0];
    const float* qkv_w  = (const float*)d_in[1];
    const float* qkv_b  = (const float*)d_in[2];
    const float* proj_w = (const float*)d_in[3];
    const float* proj_b = (const float*)d_in[4];
    const float* ffn1_w = (const float*)d_in[5];
    const float* ffn1_b = (const float*)d_in[6];
    const float* dw_w   = (const float*)d_in[7];
    const float* dw_b   = (const float*)d_in[8];
    const float* ffn2_w = (const float*)d_in[9];
    const float* ffn2_b = (const float*)d_in[10];
    float* out = (float*)d_out;

    float *p_o, *p_x1, *p_h1, *p_h2;
    cudaGetSymbolAddress((void**)&p_o,  g_o);
    cudaGetSymbolAddress((void**)&p_x1, g_x1);
    cudaGetSymbolAddress((void**)&p_h1, g_h1);
    cudaGetSymbolAddress((void**)&p_h2, g_h2);

    dim3 gpw(NPIX/128, BATCH);     // (512, 2)

    zero_kv_kernel<<<(BATCH*HEADS*KVSZ + 255)/256, 256>>>();
    pw_qkv_kernel<<<gpw, 256>>>(x, qkv_w, qkv_b);
    kv_kernel<<<dim3(HH/KV_ROWS, BATCH*HEADS), 256>>>();
    attn_kernel<<<BATCH*NPIX/1024, 256>>>();
    proj3x3_kernel<<<gpw, 256>>>(p_o, proj_w, proj_b, x, p_x1);
    pw_single_kernel<2><<<gpw, 256>>>(p_x1, ffn1_w, ffn1_b, nullptr, p_h1);
    dw_gelu_kernel<<<BATCH*C*NPIX/256, 256>>>(p_h1, dw_w, dw_b, p_h2);
    pw_single_kernel<3><<<gpw, 256>>>(p_h2, ffn2_w, ffn2_b, p_x1, out);
}

// round 10
// speedup vs baseline: 1.8875x; 1.0528x over previous
#include <cuda_runtime.h>
#include <math.h>
#include <stdint.h>

#define C        64
#define HH       256
#define WW       256
#define NPIX     65536            // HH*WW
#define BATCH    2
#define HEADS    8
#define KVSZ     648              // 72*8 + 72 per (b,h)

// -------- scratch (device globals: allocation-free at launch time) --------
__device__ float g_q [BATCH*C*NPIX];
__device__ float g_k [BATCH*C*NPIX];
__device__ float g_v [BATCH*C*NPIX];
__device__ float g_o [BATCH*C*NPIX];
__device__ float g_x1[BATCH*C*NPIX];
__device__ float g_h1[BATCH*C*NPIX];
__device__ float g_h2[BATCH*C*NPIX];
__device__ float g_kv[BATCH*HEADS*KVSZ];

__device__ __forceinline__ float gelu_exact(float v) {
    return 0.5f * v * (1.0f + erff(v * 0.7071067811865476f));
}

__device__ __forceinline__ float to_tf32(float x) {
    uint32_t u;
    asm("cvt.rna.tf32.f32 %0, %1;" : "=r"(u) : "f"(x));
    return __uint_as_float(u);
}
__device__ __forceinline__ uint32_t to_tf32_u(float x) {
    uint32_t u;
    asm("cvt.rna.tf32.f32 %0, %1;" : "=r"(u) : "f"(x));
    return u;
}

// A = 16(oc) x 8(k), row-major; B = 8(k) x 8(px), col-major; C = 16 x 8
__device__ __forceinline__ void mma_tf32(float* c,
        uint32_t a0, uint32_t a1, uint32_t a2, uint32_t a3,
        uint32_t b0, uint32_t b1) {
    asm volatile(
        "mma.sync.aligned.m16n8k8.row.col.f32.tf32.tf32.f32 "
        "{%0,%1,%2,%3}, {%4,%5,%6,%7}, {%8,%9}, {%0,%1,%2,%3};\n"
        : "+f"(c[0]), "+f"(c[1]), "+f"(c[2]), "+f"(c[3])
        : "r"(a0), "r"(a1), "r"(a2), "r"(a3), "r"(b0), "r"(b1));
}

// ---------------------------------------------------------------
__global__ void zero_kv_kernel() {
    int i = blockIdx.x * blockDim.x + threadIdx.x;
    if (i < BATCH*HEADS*KVSZ) g_kv[i] = 0.0f;
}

// ---------------------------------------------------------------
// Fused qkv pointwise GEMM: out{q,k,v}[oc][px] = act(W[oc][:]·x[:][px] + b)
// ---------------------------------------------------------------
__global__ __launch_bounds__(256)
void pw_qkv_kernel(const float* __restrict__ x,
                   const float* __restrict__ w,
                   const float* __restrict__ bias) {
    __shared__ float xs[C][136];            // 34.8 KB

    int b    = blockIdx.y;
    int pix0 = blockIdx.x * 128;
    int tid  = threadIdx.x;
    const float* inb = x + (size_t)b*C*NPIX + pix0;

    #pragma unroll
    for (int it = 0; it < 8; it++) {
        int idx = tid + it*256;
        int ic = idx >> 5, p4 = (idx & 31) << 2;
        float4 v = *(const float4*)(inb + (size_t)ic*NPIX + p4);
        v.x = to_tf32(v.x); v.y = to_tf32(v.y);
        v.z = to_tf32(v.z); v.w = to_tf32(v.w);
        *(float4*)&xs[ic][p4] = v;
    }
    __syncthreads();

    int lane = tid & 31, wid = tid >> 5;
    int g = lane >> 2, l4 = lane & 3;
    int oc0 = (wid & 3) * 16;
    int pxw = (wid >> 2) * 64;

    #pragma unroll
    for (int p = 0; p < 3; p++) {
        float* op = ((p == 0) ? g_q : (p == 1) ? g_k : g_v) + (size_t)b*C*NPIX + pix0;
        uint32_t Ar[8][4];
        const float* wp = w + (size_t)(p*C + oc0 + g)*C + l4;
        #pragma unroll
        for (int ks = 0; ks < 8; ks++) {
            Ar[ks][0] = to_tf32_u(wp[ks*8]);
            Ar[ks][1] = to_tf32_u(wp[8*C + ks*8]);
            Ar[ks][2] = to_tf32_u(wp[ks*8 + 4]);
            Ar[ks][3] = to_tf32_u(wp[8*C + ks*8 + 4]);
        }
        float b_lo = bias[p*C + oc0 + g];
        float b_hi = bias[p*C + oc0 + g + 8];

        #pragma unroll
        for (int f = 0; f < 8; f++) {
            int px0f = pxw + f*8;
            float acc[4] = {0.f, 0.f, 0.f, 0.f};
            #pragma unroll
            for (int ks = 0; ks < 8; ks++) {
                uint32_t b0 = __float_as_uint(xs[ks*8 + l4    ][px0f + g]);
                uint32_t b1 = __float_as_uint(xs[ks*8 + 4 + l4][px0f + g]);
                mma_tf32(acc, Ar[ks][0], Ar[ks][1], Ar[ks][2], Ar[ks][3], b0, b1);
            }
            float v0 = acc[0] + b_lo, v1 = acc[1] + b_lo;
            float v2 = acc[2] + b_hi, v3 = acc[3] + b_hi;
            if (p < 2) {
                v0 = fmaxf(v0, 0.f); v1 = fmaxf(v1, 0.f);
                v2 = fmaxf(v2, 0.f); v3 = fmaxf(v3, 0.f);
            }
            size_t olo = (size_t)(oc0 + g)*NPIX + px0f + 2*l4;
            *(float2*)&op[olo]          = make_float2(v0, v1);
            *(float2*)&op[olo + 8*NPIX] = make_float2(v2, v3);
        }
    }
}

// ---------------------------------------------------------------
// Single pointwise GEMM 64->64. MODE: 2 = gelu, 3 = +res.
// ---------------------------------------------------------------
template<int MODE>
__global__ __launch_bounds__(256)
void pw_single_kernel(const float* __restrict__ in,
                      const float* __restrict__ w,
                      const float* __restrict__ bias,
                      const float* __restrict__ res,
                      float* __restrict__ out) {
    __shared__ float xs[C][136];

    int b    = blockIdx.y;
    int pix0 = blockIdx.x * 128;
    int tid  = threadIdx.x;
    const float* inb = in + (size_t)b*C*NPIX + pix0;

    #pragma unroll
    for (int it = 0; it < 8; it++) {
        int idx = tid + it*256;
        int ic = idx >> 5, p4 = (idx & 31) << 2;
        float4 v = *(const float4*)(inb + (size_t)ic*NPIX + p4);
        v.x = to_tf32(v.x); v.y = to_tf32(v.y);
        v.z = to_tf32(v.z); v.w = to_tf32(v.w);
        *(float4*)&xs[ic][p4] = v;
    }
    __syncthreads();

    int lane = tid & 31, wid = tid >> 5;
    int g = lane >> 2, l4 = lane & 3;
    int oc0 = (wid & 3) * 16;
    int pxw = (wid >> 2) * 64;

    uint32_t Ar[8][4];
    const float* wp = w + (size_t)(oc0 + g)*C + l4;
    #pragma unroll
    for (int ks = 0; ks < 8; ks++) {
        Ar[ks][0] = to_tf32_u(wp[ks*8]);
        Ar[ks][1] = to_tf32_u(wp[8*C + ks*8]);
        Ar[ks][2] = to_tf32_u(wp[ks*8 + 4]);
        Ar[ks][3] = to_tf32_u(wp[8*C + ks*8 + 4]);
    }
    float b_lo = bias[oc0 + g];
    float b_hi = bias[oc0 + g + 8];
    float* op = out + (size_t)b*C*NPIX + pix0;
    const float* rp = (MODE == 3) ? res + (size_t)b*C*NPIX + pix0 : nullptr;

    #pragma unroll
    for (int f = 0; f < 8; f++) {
        int px0f = pxw + f*8;
        float acc[4] = {0.f, 0.f, 0.f, 0.f};
        #pragma unroll
        for (int ks = 0; ks < 8; ks++) {
            uint32_t b0 = __float_as_uint(xs[ks*8 + l4    ][px0f + g]);
            uint32_t b1 = __float_as_uint(xs[ks*8 + 4 + l4][px0f + g]);
            mma_tf32(acc, Ar[ks][0], Ar[ks][1], Ar[ks][2], Ar[ks][3], b0, b1);
        }
        float v0 = acc[0] + b_lo, v1 = acc[1] + b_lo;
        float v2 = acc[2] + b_hi, v3 = acc[3] + b_hi;
        size_t olo = (size_t)(oc0 + g)*NPIX + px0f + 2*l4;
        size_t ohi = olo + 8*NPIX;
        if (MODE == 2) {
            v0 = gelu_exact(v0); v1 = gelu_exact(v1);
            v2 = gelu_exact(v2); v3 = gelu_exact(v3);
        } else {
            v0 += rp[olo]; v1 += rp[olo+1];
            v2 += rp[ohi]; v3 += rp[ohi+1];
        }
        *(float2*)&op[olo] = make_float2(v0, v1);
        *(float2*)&op[ohi] = make_float2(v2, v3);
    }
}

// ---------------------------------------------------------------
// proj 3x3 conv (64->64, pad 1) + bias + residual.
// ---------------------------------------------------------------
__global__ __launch_bounds__(256)
void proj3x3_kernel(const float* __restrict__ in,
                    const float* __restrict__ w,
                    const float* __restrict__ bias,
                    const float* __restrict__ res,
                    float* __restrict__ out) {
    __shared__ float xs[16][3][136];        // 26.1 KB

    int b  = blockIdx.y;
    int y  = blockIdx.x >> 1;
    int x0 = (blockIdx.x & 1) << 7;
    int tid = threadIdx.x;
    int lane = tid & 31, wid = tid >> 5;
    int g = lane >> 2, l4 = lane & 3;
    int oc0 = (wid & 3) * 16;
    int pxw = (wid >> 2) * 64;

    const float* inb = in + (size_t)b*C*NPIX;

    float acc[8][4];
    #pragma unroll
    for (int f = 0; f < 8; f++)
        #pragma unroll
        for (int j = 0; j < 4; j++) acc[f][j] = 0.f;

    for (int ic0 = 0; ic0 < C; ic0 += 16) {
        __syncthreads();
        #pragma unroll
        for (int it = 0; it < 6; it++) {
            int idx = tid + it*256;
            int ic = idx / 96, r = idx % 96;
            int dy = r >> 5, q4 = (r & 31) << 2;
            int gy = y + dy - 1;
            float4 v = make_float4(0.f, 0.f, 0.f, 0.f);
            if (gy >= 0 && gy < HH)
                v = *(const float4*)(inb + (size_t)(ic0+ic)*NPIX + gy*WW + x0 + q4);
            xs[ic][dy][1 + q4    ] = to_tf32(v.x);
            xs[ic][dy][1 + q4 + 1] = to_tf32(v.y);
            xs[ic][dy][1 + q4 + 2] = to_tf32(v.z);
            xs[ic][dy][1 + q4 + 3] = to_tf32(v.w);
        }
        if (tid < 96) {
            int ic = tid / 6, r = tid % 6;
            int dy = r >> 1, side = r & 1;
            int xx = side ? 129 : 0;
            int gy = y + dy - 1;
            int gx = x0 + xx - 1;
            float v = 0.f;
            if (gy >= 0 && gy < HH && (unsigned)gx < WW)
                v = inb[(size_t)(ic0+ic)*NPIX + gy*WW + gx];
            xs[ic][dy][xx] = to_tf32(v);
        }
        __syncthreads();

        #pragma unroll
        for (int pp = 0; pp < 9; pp++) {
            int dy = pp / 3, dx = pp % 3;
            uint32_t Ar[2][4];
            #pragma unroll
            for (int ks = 0; ks < 2; ks++) {
                const float* wp = w + (size_t)(oc0 + g)*(C*9) + (size_t)(ic0 + ks*8 + l4)*9 + pp;
                Ar[ks][0] = to_tf32_u(wp[0]);
                Ar[ks][1] = to_tf32_u(wp[8*C*9]);
                Ar[ks][2] = to_tf32_u(wp[4*9]);
                Ar[ks][3] = to_tf32_u(wp[8*C*9 + 4*9]);
            }
            #pragma unroll
            for (int f = 0; f < 8; f++) {
                int xb = pxw + f*8 + g + dx;
                #pragma unroll
                for (int ks = 0; ks < 2; ks++) {
                    uint32_t b0 = __float_as_uint(xs[ks*8 + l4    ][dy][xb]);
                    uint32_t b1 = __float_as_uint(xs[ks*8 + 4 + l4][dy][xb]);
                    mma_tf32(acc[f], Ar[ks][0], Ar[ks][1], Ar[ks][2], Ar[ks][3], b0, b1);
                }
            }
        }
    }

    float b_lo = bias[oc0 + g];
    float b_hi = bias[oc0 + g + 8];
    size_t pbase = (size_t)b*C*NPIX + (size_t)y*WW + x0;
    #pragma unroll
    for (int f = 0; f < 8; f++) {
        int px = pxw + f*8 + 2*l4;
        size_t olo = pbase + (size_t)(oc0 + g)*NPIX + px;
        size_t ohi = olo + 8*NPIX;
        float v0 = acc[f][0] + b_lo + res[olo];
        float v1 = acc[f][1] + b_lo + res[olo+1];
        float v2 = acc[f][2] + b_hi + res[ohi];
        float v3 = acc[f][3] + b_hi + res[ohi+1];
        *(float2*)&out[olo] = make_float2(v0, v1);
        *(float2*)&out[ohi] = make_float2(v2, v3);
    }
}

// ---------------------------------------------------------------
// kv[b,h,d,e] = sum_n k_unfold[d,n] * v[e,n]  ;  ksum[b,h,d]
// ---------------------------------------------------------------
#define KV_ROWS 16
__global__ __launch_bounds__(256)
void kv_kernel() {
    int bh = blockIdx.y;
    int b  = bh >> 3;
    int h  = bh & 7;
    int warp = threadIdx.x >> 5;
    int lane = threadIdx.x & 31;
    int cl = warp;

    const float* kc = g_k + ((size_t)(b*C + 8*h + cl))*NPIX;
    const float* vb = g_v + ((size_t)(b*C + 8*h))*NPIX;

    float acc[9][8];
    float accs[9];
    #pragma unroll
    for (int p = 0; p < 9; p++) {
        accs[p] = 0.0f;
        #pragma unroll
        for (int e = 0; e < 8; e++) acc[p][e] = 0.0f;
    }

    int y0 = blockIdx.x * KV_ROWS;
    for (int y = y0; y < y0 + KV_ROWS; y++) {
        #pragma unroll 1
        for (int xi = 0; xi < 8; xi++) {
            int xx0 = lane + 32*xi;
            float vv[8];
            #pragma unroll
            for (int e = 0; e < 8; e++) vv[e] = vb[e*NPIX + y*WW + xx0];
            #pragma unroll
            for (int i = 0; i < 3; i++) {
                int yy = y + i - 1;
                if (yy < 0 || yy >= HH) continue;
                #pragma unroll
                for (int j = 0; j < 3; j++) {
                    int xj = xx0 + j - 1;
                    if (xj < 0 || xj >= WW) continue;
                    float kl = kc[yy*WW + xj];
                    int pp = i*3 + j;
                    accs[pp] += kl;
                    #pragma unroll
                    for (int e = 0; e < 8; e++)
                        acc[pp][e] = fmaf(kl, vv[e], acc[pp][e]);
                }
            }
        }
    }

    #pragma unroll
    for (int pp = 0; pp < 9; pp++) {
        #pragma unroll
        for (int e = 0; e < 8; e++) {
            float v = acc[pp][e];
            for (int s = 16; s > 0; s >>= 1) v += __shfl_xor_sync(0xffffffffu, v, s);
            acc[pp][e] = v;
        }
        float v = accs[pp];
        for (int s = 16; s > 0; s >>= 1) v += __shfl_xor_sync(0xffffffffu, v, s);
        accs[pp] = v;
    }

    if (lane == 0) {
        float* outp = g_kv + bh*KVSZ;
        #pragma unroll
        for (int pp = 0; pp < 9; pp++) {
            int d = cl*9 + pp;
            #pragma unroll
            for (int e = 0; e < 8; e++) atomicAdd(&outp[d*8 + e], acc[pp][e]);
            atomicAdd(&outp[576 + d], accs[pp]);
        }
    }
}

// ---------------------------------------------------------------
// per-pixel attention; 4 consecutive pixels per thread, 2 heads per block.
// grid: (64 px-chunks, 4 head-groups, BATCH) = 512 blocks.
// ---------------------------------------------------------------
__global__ __launch_bounds__(256)
void attn_kernel() {
    int b    = blockIdx.z;
    int hg   = blockIdx.y;                      // head group: heads hg*2, hg*2+1
    int base = blockIdx.x * 1024;
    __shared__ float kvs[2*KVSZ];               // 5.2 KB
    for (int i = threadIdx.x; i < 2*KVSZ; i += 256)
        kvs[i] = g_kv[(size_t)(b*HEADS + hg*2)*KVSZ + i];
    __syncthreads();

    int n0  = base + threadIdx.x * 4;
    int y   = n0 >> 8;
    int xx0 = n0 & 255;                         // multiple of 4, same row for 4 px
    const float* qb = g_q + (size_t)b*C*NPIX;

    #pragma unroll 1
    for (int hi = 0; hi < 2; hi++) {
        int h = hg*2 + hi;
        float num[4][8];
        float den[4] = {0.f, 0.f, 0.f, 0.f};
        #pragma unroll
        for (int t = 0; t < 4; t++)
            #pragma unroll
            for (int e = 0; e < 8; e++) num[t][e] = 0.f;

        const float* kvh = kvs + hi*KVSZ;
        #pragma unroll 1
        for (int cl = 0; cl < 8; cl++) {
            const float* qc = qb + (size_t)(8*h + cl)*NPIX;
            #pragma unroll
            for (int i = 0; i < 3; i++) {
                int yy = y + i - 1;
                if (yy < 0 || yy >= HH) continue;
                const float* qr = qc + yy*WW;
                float qrow[6];
                #pragma unroll
                for (int t = 0; t < 6; t++) {
                    int gx = xx0 - 1 + t;
                    qrow[t] = ((unsigned)gx < WW) ? qr[gx] : 0.f;
                }
                #pragma unroll
                for (int j = 0; j < 3; j++) {
                    int d = cl*9 + i*3 + j;
                    float ks = kvh[576 + d];
                    const float* kvd = kvh + d*8;
                    #pragma unroll
                    for (int t = 0; t < 4; t++) {
                        float qv = qrow[t + j];
                        den[t] = fmaf(qv, ks, den[t]);
                        #pragma unroll
                        for (int e = 0; e < 8; e++)
                            num[t][e] = fmaf(qv, kvd[e], num[t][e]);
                    }
                }
            }
        }
        float inv[4];
        #pragma unroll
        for (int t = 0; t < 4; t++) inv[t] = 1.0f / (den[t] + 1e-6f);
        #pragma unroll
        for (int e = 0; e < 8; e++) {
            float4 v = make_float4(num[0][e]*inv[0], num[1][e]*inv[1],
                                   num[2][e]*inv[2], num[3][e]*inv[3]);
            *(float4*)&g_o[(size_t)(b*C + 8*h + e)*NPIX + n0] = v;
        }
    }
}

// ---------------------------------------------------------------
// depthwise 3x3 conv (pad 1) + bias + exact GELU; 4 px/thread.
// ---------------------------------------------------------------
__global__ __launch_bounds__(256)
void dw_gelu_kernel(const float* __restrict__ in,
                    const float* __restrict__ w,
                    const float* __restrict__ bias,
                    float* __restrict__ out) {
    int idx = blockIdx.x * 256 + threadIdx.x;
    int n   = idx * 4;                          // (b*C+c)*NPIX + y*W + x
    int x   = n & 255;
    int y   = (n >> 8) & 255;
    int bc  = n >> 16;
    int c   = bc & (C - 1);
    const float* ib = in + (size_t)bc*NPIX;

    float bv = bias[c];
    float a[4] = {bv, bv, bv, bv};
    #pragma unroll
    for (int i = 0; i < 3; i++) {
        int yy = y + i - 1;
        if (yy < 0 || yy >= HH) continue;
        const float* r = ib + yy*WW;
        float row[6];
        row[0] = (x > 0) ? r[x-1] : 0.f;
        float4 m = *(const float4*)&r[x];
        row[1] = m.x; row[2] = m.y; row[3] = m.z; row[4] = m.w;
        row[5] = (x + 4 < WW) ? r[x+4] : 0.f;
        #pragma unroll
        for (int j = 0; j < 3; j++) {
            float wv = w[c*9 + i*3 + j];
            #pragma unroll
            for (int t = 0; t < 4; t++)
                a[t] = fmaf(wv, row[t + j], a[t]);
        }
    }
    float4 o = make_float4(gelu_exact(a[0]), gelu_exact(a[1]),
                           gelu_exact(a[2]), gelu_exact(a[3]));
    *(float4*)&out[(size_t)n] = o;
}

// ---------------------------------------------------------------
extern "C" void kernel_launch(void* const* d_in, const int* in_sizes, int n_in,
                              void* d_out, int out_size) {
    const float* x      = (const float*)d_in[0];
    const float* qkv_w  = (const float*)d_in[1];
    const float* qkv_b  = (const float*)d_in[2];
    const float* proj_w = (const float*)d_in[3];
    const float* proj_b = (const float*)d_in[4];
    const float* ffn1_w = (const float*)d_in[5];
    const float* ffn1_b = (const float*)d_in[6];
    const float* dw_w   = (const float*)d_in[7];
    const float* dw_b   = (const float*)d_in[8];
    const float* ffn2_w = (const float*)d_in[9];
    const float* ffn2_b = (const float*)d_in[10];
    float* out = (float*)d_out;

    float *p_o, *p_x1, *p_h1, *p_h2;
    cudaGetSymbolAddress((void**)&p_o,  g_o);
    cudaGetSymbolAddress((void**)&p_x1, g_x1);
    cudaGetSymbolAddress((void**)&p_h1, g_h1);
    cudaGetSymbolAddress((void**)&p_h2, g_h2);

    dim3 gpw(NPIX/128, BATCH);     // (512, 2)

    zero_kv_kernel<<<(BATCH*HEADS*KVSZ + 255)/256, 256>>>();
    pw_qkv_kernel<<<gpw, 256>>>(x, qkv_w, qkv_b);
    kv_kernel<<<dim3(HH/KV_ROWS, BATCH*HEADS), 256>>>();
    attn_kernel<<<dim3(64, 4, BATCH), 256>>>();
    proj3x3_kernel<<<gpw, 256>>>(p_o, proj_w, proj_b, x, p_x1);
    pw_single_kernel<2><<<gpw, 256>>>(p_x1, ffn1_w, ffn1_b, nullptr, p_h1);
    dw_gelu_kernel<<<BATCH*C*NPIX/1024, 256>>>(p_h1, dw_w, dw_b, p_h2);
    pw_single_kernel<3><<<gpw, 256>>>(p_h2, ffn2_w, ffn2_b, p_x1, out);
}

// round 11
// speedup vs baseline: 2.1873x; 1.1588x over previous
#include <cuda_runtime.h>
#include <cuda_bf16.h>
#include <math.h>
#include <stdint.h>

#define C        64
#define HH       256
#define WW       256
#define NPIX     65536            // HH*WW
#define BATCH    2
#define HEADS    8
#define KVSZ     648              // 72*8 + 72 per (b,h)

// -------- scratch (device globals: allocation-free at launch time) --------
__device__ float g_q [BATCH*C*NPIX];
__device__ float g_k [BATCH*C*NPIX];
__device__ float g_v [BATCH*C*NPIX];
__device__ float g_o [BATCH*C*NPIX];
__device__ float g_x1[BATCH*C*NPIX];
__device__ float g_h1[BATCH*C*NPIX];
__device__ float g_h2[BATCH*C*NPIX];
__device__ float g_kv[BATCH*HEADS*KVSZ];

__device__ __forceinline__ float gelu_exact(float v) {
    return 0.5f * v * (1.0f + erff(v * 0.7071067811865476f));
}

// pack two floats into bf16x2 (lo = first/even-k element, hi = second)
__device__ __forceinline__ uint32_t packbf(float lo, float hi) {
    __nv_bfloat162 t = __floats2bfloat162_rn(lo, hi);   // .x = lo (low 16b)
    return *reinterpret_cast<uint32_t*>(&t);
}

// m16n8k16 bf16 MMA, fp32 accum.
// A (16x16) row-major: a0={A[g][2l],A[g][2l+1]} a1={A[g+8][..]} a2={A[g][2l+8..]} a3={A[g+8][2l+8..]}
// B (16x8)  col-major: b0={B[2l][g],B[2l+1][g]} b1={B[2l+8][g],B[2l+9][g]}
// C (16x8): c0=(g,2l) c1=(g,2l+1) c2=(g+8,2l) c3=(g+8,2l+1)
__device__ __forceinline__ void mma_bf16(float* c,
        uint32_t a0, uint32_t a1, uint32_t a2, uint32_t a3,
        uint32_t b0, uint32_t b1) {
    asm volatile(
        "mma.sync.aligned.m16n8k16.row.col.f32.bf16.bf16.f32 "
        "{%0,%1,%2,%3}, {%4,%5,%6,%7}, {%8,%9}, {%0,%1,%2,%3};\n"
        : "+f"(c[0]), "+f"(c[1]), "+f"(c[2]), "+f"(c[3])
        : "r"(a0), "r"(a1), "r"(a2), "r"(a3), "r"(b0), "r"(b1));
}

// ---------------------------------------------------------------
__global__ void zero_kv_kernel() {
    int i = blockIdx.x * blockDim.x + threadIdx.x;
    if (i < BATCH*HEADS*KVSZ) g_kv[i] = 0.0f;
}

// ---------------------------------------------------------------
// Fused qkv pointwise GEMM (bf16 MMA): out{q,k,v} = act(W·x + b)
// Block: 256 thr = 8 warps, 128 contiguous px, all 192 oc.
// xsp: k-pairs packed bf16x2, [kk=ic/2][px].
// ---------------------------------------------------------------
__global__ __launch_bounds__(256)
void pw_qkv_kernel(const float* __restrict__ x,
                   const float* __restrict__ w,
                   const float* __restrict__ bias) {
    __shared__ uint32_t xsp[C/2][136];      // 17.4 KB

    int b    = blockIdx.y;
    int pix0 = blockIdx.x * 128;
    int tid  = threadIdx.x;
    const float* inb = x + (size_t)b*C*NPIX + pix0;

    #pragma unroll
    for (int it = 0; it < 4; it++) {
        int idx = tid + it*256;             // 0..1023
        int kk = idx >> 5, p4 = (idx & 31) << 2;
        float4 e = *(const float4*)(inb + (size_t)(2*kk    )*NPIX + p4);
        float4 o = *(const float4*)(inb + (size_t)(2*kk + 1)*NPIX + p4);
        uint4 st;
        st.x = packbf(e.x, o.x); st.y = packbf(e.y, o.y);
        st.z = packbf(e.z, o.z); st.w = packbf(e.w, o.w);
        *(uint4*)&xsp[kk][p4] = st;
    }
    __syncthreads();

    int lane = tid & 31, wid = tid >> 5;
    int g = lane >> 2, l4 = lane & 3;
    int oc0 = (wid & 3) * 16;
    int pxw = (wid >> 2) * 64;

    #pragma unroll
    for (int p = 0; p < 3; p++) {
        float* op = ((p == 0) ? g_q : (p == 1) ? g_k : g_v) + (size_t)b*C*NPIX + pix0;
        // A frags: 4 ksteps of 16
        uint32_t Ar[4][4];
        const float* wp0 = w + (size_t)(p*C + oc0 + g)*C;
        const float* wp1 = wp0 + 8*C;
        #pragma unroll
        for (int s = 0; s < 4; s++) {
            float2 e0 = *(const float2*)(wp0 + 16*s + 2*l4);
            float2 e1 = *(const float2*)(wp1 + 16*s + 2*l4);
            float2 e2 = *(const float2*)(wp0 + 16*s + 2*l4 + 8);
            float2 e3 = *(const float2*)(wp1 + 16*s + 2*l4 + 8);
            Ar[s][0] = packbf(e0.x, e0.y);
            Ar[s][1] = packbf(e1.x, e1.y);
            Ar[s][2] = packbf(e2.x, e2.y);
            Ar[s][3] = packbf(e3.x, e3.y);
        }
        float b_lo = bias[p*C + oc0 + g];
        float b_hi = bias[p*C + oc0 + g + 8];

        #pragma unroll
        for (int f = 0; f < 8; f++) {
            int px0f = pxw + f*8;
            float acc[4] = {0.f, 0.f, 0.f, 0.f};
            #pragma unroll
            for (int s = 0; s < 4; s++) {
                uint32_t b0 = xsp[s*8 + l4    ][px0f + g];
                uint32_t b1 = xsp[s*8 + l4 + 4][px0f + g];
                mma_bf16(acc, Ar[s][0], Ar[s][1], Ar[s][2], Ar[s][3], b0, b1);
            }
            float v0 = acc[0] + b_lo, v1 = acc[1] + b_lo;
            float v2 = acc[2] + b_hi, v3 = acc[3] + b_hi;
            if (p < 2) {
                v0 = fmaxf(v0, 0.f); v1 = fmaxf(v1, 0.f);
                v2 = fmaxf(v2, 0.f); v3 = fmaxf(v3, 0.f);
            }
            size_t olo = (size_t)(oc0 + g)*NPIX + px0f + 2*l4;
            *(float2*)&op[olo]          = make_float2(v0, v1);
            *(float2*)&op[olo + 8*NPIX] = make_float2(v2, v3);
        }
    }
}

// ---------------------------------------------------------------
// Single pointwise GEMM 64->64 (bf16 MMA). MODE: 2 = gelu, 3 = +res.
// ---------------------------------------------------------------
template<int MODE>
__global__ __launch_bounds__(256)
void pw_single_kernel(const float* __restrict__ in,
                      const float* __restrict__ w,
                      const float* __restrict__ bias,
                      const float* __restrict__ res,
                      float* __restrict__ out) {
    __shared__ uint32_t xsp[C/2][136];

    int b    = blockIdx.y;
    int pix0 = blockIdx.x * 128;
    int tid  = threadIdx.x;
    const float* inb = in + (size_t)b*C*NPIX + pix0;

    #pragma unroll
    for (int it = 0; it < 4; it++) {
        int idx = tid + it*256;
        int kk = idx >> 5, p4 = (idx & 31) << 2;
        float4 e = *(const float4*)(inb + (size_t)(2*kk    )*NPIX + p4);
        float4 o = *(const float4*)(inb + (size_t)(2*kk + 1)*NPIX + p4);
        uint4 st;
        st.x = packbf(e.x, o.x); st.y = packbf(e.y, o.y);
        st.z = packbf(e.z, o.z); st.w = packbf(e.w, o.w);
        *(uint4*)&xsp[kk][p4] = st;
    }
    __syncthreads();

    int lane = tid & 31, wid = tid >> 5;
    int g = lane >> 2, l4 = lane & 3;
    int oc0 = (wid & 3) * 16;
    int pxw = (wid >> 2) * 64;

    uint32_t Ar[4][4];
    const float* wp0 = w + (size_t)(oc0 + g)*C;
    const float* wp1 = wp0 + 8*C;
    #pragma unroll
    for (int s = 0; s < 4; s++) {
        float2 e0 = *(const float2*)(wp0 + 16*s + 2*l4);
        float2 e1 = *(const float2*)(wp1 + 16*s + 2*l4);
        float2 e2 = *(const float2*)(wp0 + 16*s + 2*l4 + 8);
        float2 e3 = *(const float2*)(wp1 + 16*s + 2*l4 + 8);
        Ar[s][0] = packbf(e0.x, e0.y);
        Ar[s][1] = packbf(e1.x, e1.y);
        Ar[s][2] = packbf(e2.x, e2.y);
        Ar[s][3] = packbf(e3.x, e3.y);
    }
    float b_lo = bias[oc0 + g];
    float b_hi = bias[oc0 + g + 8];
    float* op = out + (size_t)b*C*NPIX + pix0;
    const float* rp = (MODE == 3) ? res + (size_t)b*C*NPIX + pix0 : nullptr;

    #pragma unroll
    for (int f = 0; f < 8; f++) {
        int px0f = pxw + f*8;
        float acc[4] = {0.f, 0.f, 0.f, 0.f};
        #pragma unroll
        for (int s = 0; s < 4; s++) {
            uint32_t b0 = xsp[s*8 + l4    ][px0f + g];
            uint32_t b1 = xsp[s*8 + l4 + 4][px0f + g];
            mma_bf16(acc, Ar[s][0], Ar[s][1], Ar[s][2], Ar[s][3], b0, b1);
        }
        float v0 = acc[0] + b_lo, v1 = acc[1] + b_lo;
        float v2 = acc[2] + b_hi, v3 = acc[3] + b_hi;
        size_t olo = (size_t)(oc0 + g)*NPIX + px0f + 2*l4;
        size_t ohi = olo + 8*NPIX;
        if (MODE == 2) {
            v0 = gelu_exact(v0); v1 = gelu_exact(v1);
            v2 = gelu_exact(v2); v3 = gelu_exact(v3);
        } else {
            v0 += rp[olo]; v1 += rp[olo+1];
            v2 += rp[ohi]; v3 += rp[ohi+1];
        }
        *(float2*)&op[olo] = make_float2(v0, v1);
        *(float2*)&op[ohi] = make_float2(v2, v3);
    }
}

// ---------------------------------------------------------------
// proj 3x3 conv (64->64, pad 1) + bias + residual (bf16 MMA).
// ic-chunk 16 = ONE k16 step; xsp packs ic-pairs.
// ---------------------------------------------------------------
__global__ __launch_bounds__(256)
void proj3x3_kernel(const float* __restrict__ in,
                    const float* __restrict__ w,
                    const float* __restrict__ bias,
                    const float* __restrict__ res,
                    float* __restrict__ out) {
    __shared__ uint32_t xsp[8][3][136];     // 13 KB; xx index: gx = x0 + xx - 1

    int b  = blockIdx.y;
    int y  = blockIdx.x >> 1;
    int x0 = (blockIdx.x & 1) << 7;
    int tid = threadIdx.x;
    int lane = tid & 31, wid = tid >> 5;
    int g = lane >> 2, l4 = lane & 3;
    int oc0 = (wid & 3) * 16;
    int pxw = (wid >> 2) * 64;

    const float* inb = in + (size_t)b*C*NPIX;

    float acc[8][4];
    #pragma unroll
    for (int f = 0; f < 8; f++)
        #pragma unroll
        for (int j = 0; j < 4; j++) acc[f][j] = 0.f;

    for (int ic0 = 0; ic0 < C; ic0 += 16) {
        __syncthreads();
        // interior: 8 ic-pairs x 3 dy x 32 float4-quads = 768 items
        #pragma unroll
        for (int it = 0; it < 3; it++) {
            int idx = tid + it*256;
            int icp = idx / 96, r = idx % 96;
            int dy = r >> 5, q4 = (r & 31) << 2;
            int gy = y + dy - 1;
            float4 e = make_float4(0.f, 0.f, 0.f, 0.f);
            float4 o = make_float4(0.f, 0.f, 0.f, 0.f);
            if (gy >= 0 && gy < HH) {
                e = *(const float4*)(inb + (size_t)(ic0 + 2*icp    )*NPIX + gy*WW + x0 + q4);
                o = *(const float4*)(inb + (size_t)(ic0 + 2*icp + 1)*NPIX + gy*WW + x0 + q4);
            }
            xsp[icp][dy][1 + q4    ] = packbf(e.x, o.x);
            xsp[icp][dy][1 + q4 + 1] = packbf(e.y, o.y);
            xsp[icp][dy][1 + q4 + 2] = packbf(e.z, o.z);
            xsp[icp][dy][1 + q4 + 3] = packbf(e.w, o.w);
        }
        // halo: 8 icp x 3 dy x 2 sides = 48 items
        if (tid < 48) {
            int icp = tid / 6, r = tid % 6;
            int dy = r >> 1, side = r & 1;
            int xx = side ? 129 : 0;
            int gy = y + dy - 1;
            int gx = x0 + xx - 1;
            float e = 0.f, o = 0.f;
            if (gy >= 0 && gy < HH && (unsigned)gx < WW) {
                e = inb[(size_t)(ic0 + 2*icp    )*NPIX + gy*WW + gx];
                o = inb[(size_t)(ic0 + 2*icp + 1)*NPIX + gy*WW + gx];
            }
            xsp[icp][dy][xx] = packbf(e, o);
        }
        __syncthreads();

        #pragma unroll
        for (int pp = 0; pp < 9; pp++) {
            int dy = pp / 3, dx = pp % 3;
            // A frag: one k16 step over ic0..ic0+15
            const float* wb0 = w + (size_t)(oc0 + g)*(C*9) + pp;       // + ic*9
            const float* wb1 = wb0 + (size_t)8*C*9;
            uint32_t a0 = packbf(wb0[(ic0 + 2*l4    )*9], wb0[(ic0 + 2*l4 + 1)*9]);
            uint32_t a1 = packbf(wb1[(ic0 + 2*l4    )*9], wb1[(ic0 + 2*l4 + 1)*9]);
            uint32_t a2 = packbf(wb0[(ic0 + 2*l4 + 8)*9], wb0[(ic0 + 2*l4 + 9)*9]);
            uint32_t a3 = packbf(wb1[(ic0 + 2*l4 + 8)*9], wb1[(ic0 + 2*l4 + 9)*9]);
            #pragma unroll
            for (int f = 0; f < 8; f++) {
                int xb = pxw + f*8 + g + dx;
                uint32_t b0 = xsp[l4    ][dy][xb];
                uint32_t b1 = xsp[l4 + 4][dy][xb];
                mma_bf16(acc[f], a0, a1, a2, a3, b0, b1);
            }
        }
    }

    float b_lo = bias[oc0 + g];
    float b_hi = bias[oc0 + g + 8];
    size_t pbase = (size_t)b*C*NPIX + (size_t)y*WW + x0;
    #pragma unroll
    for (int f = 0; f < 8; f++) {
        int px = pxw + f*8 + 2*l4;
        size_t olo = pbase + (size_t)(oc0 + g)*NPIX + px;
        size_t ohi = olo + 8*NPIX;
        float v0 = acc[f][0] + b_lo + res[olo];
        float v1 = acc[f][1] + b_lo + res[olo+1];
        float v2 = acc[f][2] + b_hi + res[ohi];
        float v3 = acc[f][3] + b_hi + res[ohi+1];
        *(float2*)&out[olo] = make_float2(v0, v1);
        *(float2*)&out[ohi] = make_float2(v2, v3);
    }
}

// ---------------------------------------------------------------
// kv[b,h,d,e] = sum_n k_unfold[d,n] * v[e,n]  ;  ksum[b,h,d]
// ---------------------------------------------------------------
#define KV_ROWS 16
__global__ __launch_bounds__(256)
void kv_kernel() {
    int bh = blockIdx.y;
    int b  = bh >> 3;
    int h  = bh & 7;
    int warp = threadIdx.x >> 5;
    int lane = threadIdx.x & 31;
    int cl = warp;

    const float* kc = g_k + ((size_t)(b*C + 8*h + cl))*NPIX;
    const float* vb = g_v + ((size_t)(b*C + 8*h))*NPIX;

    float acc[9][8];
    float accs[9];
    #pragma unroll
    for (int p = 0; p < 9; p++) {
        accs[p] = 0.0f;
        #pragma unroll
        for (int e = 0; e < 8; e++) acc[p][e] = 0.0f;
    }

    int y0 = blockIdx.x * KV_ROWS;
    for (int y = y0; y < y0 + KV_ROWS; y++) {
        #pragma unroll 1
        for (int xi = 0; xi < 8; xi++) {
            int xx0 = lane + 32*xi;
            float vv[8];
            #pragma unroll
            for (int e = 0; e < 8; e++) vv[e] = vb[e*NPIX + y*WW + xx0];
            #pragma unroll
            for (int i = 0; i < 3; i++) {
                int yy = y + i - 1;
                if (yy < 0 || yy >= HH) continue;
                #pragma unroll
                for (int j = 0; j < 3; j++) {
                    int xj = xx0 + j - 1;
                    if (xj < 0 || xj >= WW) continue;
                    float kl = kc[yy*WW + xj];
                    int pp = i*3 + j;
                    accs[pp] += kl;
                    #pragma unroll
                    for (int e = 0; e < 8; e++)
                        acc[pp][e] = fmaf(kl, vv[e], acc[pp][e]);
                }
            }
        }
    }

    #pragma unroll
    for (int pp = 0; pp < 9; pp++) {
        #pragma unroll
        for (int e = 0; e < 8; e++) {
            float v = acc[pp][e];
            for (int s = 16; s > 0; s >>= 1) v += __shfl_xor_sync(0xffffffffu, v, s);
            acc[pp][e] = v;
        }
        float v = accs[pp];
        for (int s = 16; s > 0; s >>= 1) v += __shfl_xor_sync(0xffffffffu, v, s);
        accs[pp] = v;
    }

    if (lane == 0) {
        float* outp = g_kv + bh*KVSZ;
        #pragma unroll
        for (int pp = 0; pp < 9; pp++) {
            int d = cl*9 + pp;
            #pragma unroll
            for (int e = 0; e < 8; e++) atomicAdd(&outp[d*8 + e], acc[pp][e]);
            atomicAdd(&outp[576 + d], accs[pp]);
        }
    }
}

// ---------------------------------------------------------------
// per-pixel attention; 4 px/thread, 2 heads/block.
// float4 kv reads (32B-aligned), float4 qrow loads.
// ---------------------------------------------------------------
__global__ __launch_bounds__(256)
void attn_kernel() {
    int b    = blockIdx.z;
    int hg   = blockIdx.y;
    int base = blockIdx.x * 1024;
    __shared__ __align__(16) float kvs[2*KVSZ];     // 5.2 KB
    for (int i = threadIdx.x; i < 2*KVSZ; i += 256)
        kvs[i] = g_kv[(size_t)(b*HEADS + hg*2)*KVSZ + i];
    __syncthreads();

    int n0  = base + threadIdx.x * 4;
    int y   = n0 >> 8;
    int xx0 = n0 & 255;                             // multiple of 4
    const float* qb = g_q + (size_t)b*C*NPIX;

    #pragma unroll 1
    for (int hi = 0; hi < 2; hi++) {
        int h = hg*2 + hi;
        float num[4][8];
        float den[4] = {0.f, 0.f, 0.f, 0.f};
        #pragma unroll
        for (int t = 0; t < 4; t++)
            #pragma unroll
            for (int e = 0; e < 8; e++) num[t][e] = 0.f;

        const float* kvh = kvs + hi*KVSZ;
        #pragma unroll 1
        for (int cl = 0; cl < 8; cl++) {
            const float* qc = qb + (size_t)(8*h + cl)*NPIX;
            #pragma unroll
            for (int i = 0; i < 3; i++) {
                int yy = y + i - 1;
                if (yy < 0 || yy >= HH) continue;
                const float* qr = qc + yy*WW;
                float qrow[6];
                qrow[0] = (xx0 > 0) ? qr[xx0 - 1] : 0.f;
                float4 m = *(const float4*)&qr[xx0];
                qrow[1] = m.x; qrow[2] = m.y; qrow[3] = m.z; qrow[4] = m.w;
                qrow[5] = (xx0 + 4 < WW) ? qr[xx0 + 4] : 0.f;
                #pragma unroll
                for (int j = 0; j < 3; j++) {
                    int d = cl*9 + i*3 + j;
                    float ksv = kvh[576 + d];
                    float4 klo = *(const float4*)(kvh + d*8);
                    float4 khi = *(const float4*)(kvh + d*8 + 4);
                    #pragma unroll
                    for (int t = 0; t < 4; t++) {
                        float qv = qrow[t + j];
                        den[t]    = fmaf(qv, ksv,   den[t]);
                        num[t][0] = fmaf(qv, klo.x, num[t][0]);
                        num[t][1] = fmaf(qv, klo.y, num[t][1]);
                        num[t][2] = fmaf(qv, klo.z, num[t][2]);
                        num[t][3] = fmaf(qv, klo.w, num[t][3]);
                        num[t][4] = fmaf(qv, khi.x, num[t][4]);
                        num[t][5] = fmaf(qv, khi.y, num[t][5]);
                        num[t][6] = fmaf(qv, khi.z, num[t][6]);
                        num[t][7] = fmaf(qv, khi.w, num[t][7]);
                    }
                }
            }
        }
        float inv[4];
        #pragma unroll
        for (int t = 0; t < 4; t++) inv[t] = 1.0f / (den[t] + 1e-6f);
        #pragma unroll
        for (int e = 0; e < 8; e++) {
            float4 v = make_float4(num[0][e]*inv[0], num[1][e]*inv[1],
                                   num[2][e]*inv[2], num[3][e]*inv[3]);
            *(float4*)&g_o[(size_t)(b*C + 8*h + e)*NPIX + n0] = v;
        }
    }
}

// ---------------------------------------------------------------
// depthwise 3x3 conv (pad 1) + bias + exact GELU; 4 px/thread.
// ---------------------------------------------------------------
__global__ __launch_bounds__(256)
void dw_gelu_kernel(const float* __restrict__ in,
                    const float* __restrict__ w,
                    const float* __restrict__ bias,
                    float* __restrict__ out) {
    int idx = blockIdx.x * 256 + threadIdx.x;
    int n   = idx * 4;
    int x   = n & 255;
    int y   = (n >> 8) & 255;
    int bc  = n >> 16;
    int c   = bc & (C - 1);
    const float* ib = in + (size_t)bc*NPIX;

    float bv = bias[c];
    float a[4] = {bv, bv, bv, bv};
    #pragma unroll
    for (int i = 0; i < 3; i++) {
        int yy = y + i - 1;
        if (yy < 0 || yy >= HH) continue;
        const float* r = ib + yy*WW;
        float row[6];
        row[0] = (x > 0) ? r[x-1] : 0.f;
        float4 m = *(const float4*)&r[x];
        row[1] = m.x; row[2] = m.y; row[3] = m.z; row[4] = m.w;
        row[5] = (x + 4 < WW) ? r[x+4] : 0.f;
        #pragma unroll
        for (int j = 0; j < 3; j++) {
            float wv = w[c*9 + i*3 + j];
            #pragma unroll
            for (int t = 0; t < 4; t++)
                a[t] = fmaf(wv, row[t + j], a[t]);
        }
    }
    float4 o = make_float4(gelu_exact(a[0]), gelu_exact(a[1]),
                           gelu_exact(a[2]), gelu_exact(a[3]));
    *(float4*)&out[(size_t)n] = o;
}

// ---------------------------------------------------------------
extern "C" void kernel_launch(void* const* d_in, const int* in_sizes, int n_in,
                              void* d_out, int out_size) {
    const float* x      = (const float*)d_in[0];
    const float* qkv_w  = (const float*)d_in[1];
    const float* qkv_b  = (const float*)d_in[2];
    const float* proj_w = (const float*)d_in[3];
    const float* proj_b = (const float*)d_in[4];
    const float* ffn1_w = (const float*)d_in[5];
    const float* ffn1_b = (const float*)d_in[6];
    const float* dw_w   = (const float*)d_in[7];
    const float* dw_b   = (const float*)d_in[8];
    const float* ffn2_w = (const float*)d_in[9];
    const float* ffn2_b = (const float*)d_in[10];
    float* out = (float*)d_out;

    float *p_o, *p_x1, *p_h1, *p_h2;
    cudaGetSymbolAddress((void**)&p_o,  g_o);
    cudaGetSymbolAddress((void**)&p_x1, g_x1);
    cudaGetSymbolAddress((void**)&p_h1, g_h1);
    cudaGetSymbolAddress((void**)&p_h2, g_h2);

    dim3 gpw(NPIX/128, BATCH);     // (512, 2)

    zero_kv_kernel<<<(BATCH*HEADS*KVSZ + 255)/256, 256>>>();
    pw_qkv_kernel<<<gpw, 256>>>(x, qkv_w, qkv_b);
    kv_kernel<<<dim3(HH/KV_ROWS, BATCH*HEADS), 256>>>();
    attn_kernel<<<dim3(64, 4, BATCH), 256>>>();
    proj3x3_kernel<<<gpw, 256>>>(p_o, proj_w, proj_b, x, p_x1);
    pw_single_kernel<2><<<gpw, 256>>>(p_x1, ffn1_w, ffn1_b, nullptr, p_h1);
    dw_gelu_kernel<<<BATCH*C*NPIX/1024, 256>>>(p_h1, dw_w, dw_b, p_h2);
    pw_single_kernel<3><<<gpw, 256>>>(p_h2, ffn2_w, ffn2_b, p_x1, out);
}

// round 12
// speedup vs baseline: 2.3886x; 1.0921x over previous
#include <cuda_runtime.h>
#include <cuda_bf16.h>
#include <math.h>
#include <stdint.h>

#define C        64
#define HH       256
#define WW       256
#define NPIX     65536            // HH*WW
#define BATCH    2
#define HEADS    8
#define KVSZ     648              // 72*8 + 72 per (b,h)

// -------- scratch (device globals: allocation-free at launch time) --------
__device__ float g_q [BATCH*C*NPIX];
__device__ float g_k [BATCH*C*NPIX];
__device__ float g_v [BATCH*C*NPIX];
__device__ float g_o [BATCH*C*NPIX];
__device__ float g_x1[BATCH*C*NPIX];
__device__ float g_h1[BATCH*C*NPIX];
__device__ float g_h2[BATCH*C*NPIX];
__device__ float g_kv[BATCH*HEADS*KVSZ];

__device__ __forceinline__ float gelu_exact(float v) {
    return 0.5f * v * (1.0f + erff(v * 0.7071067811865476f));
}

// pack two floats into bf16x2 (lo = first/even element, hi = second)
__device__ __forceinline__ uint32_t packbf(float lo, float hi) {
    __nv_bfloat162 t = __floats2bfloat162_rn(lo, hi);   // .x = lo (low 16b)
    return *reinterpret_cast<uint32_t*>(&t);
}

// m16n8k16 bf16 MMA, fp32 accum.
// A (16x16) row-major: a0={A[g][2l],A[g][2l+1]} a1={A[g+8][..]} a2={A[g][2l+8..]} a3={A[g+8][2l+8..]}
// B (16x8)  col-major: b0={B[2l][g],B[2l+1][g]} b1={B[2l+8][g],B[2l+9][g]}
// C (16x8): c0=(g,2l) c1=(g,2l+1) c2=(g+8,2l) c3=(g+8,2l+1)
__device__ __forceinline__ void mma_bf16(float* c,
        uint32_t a0, uint32_t a1, uint32_t a2, uint32_t a3,
        uint32_t b0, uint32_t b1) {
    asm volatile(
        "mma.sync.aligned.m16n8k16.row.col.f32.bf16.bf16.f32 "
        "{%0,%1,%2,%3}, {%4,%5,%6,%7}, {%8,%9}, {%0,%1,%2,%3};\n"
        : "+f"(c[0]), "+f"(c[1]), "+f"(c[2]), "+f"(c[3])
        : "r"(a0), "r"(a1), "r"(a2), "r"(a3), "r"(b0), "r"(b1));
}

// ---------------------------------------------------------------
__global__ void zero_kv_kernel() {
    int i = blockIdx.x * blockDim.x + threadIdx.x;
    if (i < BATCH*HEADS*KVSZ) g_kv[i] = 0.0f;
}

// ---------------------------------------------------------------
// Fused qkv pointwise GEMM (bf16 MMA): out{q,k,v} = act(W·x + b)
// ---------------------------------------------------------------
__global__ __launch_bounds__(256)
void pw_qkv_kernel(const float* __restrict__ x,
                   const float* __restrict__ w,
                   const float* __restrict__ bias) {
    __shared__ uint32_t xsp[C/2][136];      // 17.4 KB

    int b    = blockIdx.y;
    int pix0 = blockIdx.x * 128;
    int tid  = threadIdx.x;
    const float* inb = x + (size_t)b*C*NPIX + pix0;

    #pragma unroll
    for (int it = 0; it < 4; it++) {
        int idx = tid + it*256;             // 0..1023
        int kk = idx >> 5, p4 = (idx & 31) << 2;
        float4 e = *(const float4*)(inb + (size_t)(2*kk    )*NPIX + p4);
        float4 o = *(const float4*)(inb + (size_t)(2*kk + 1)*NPIX + p4);
        uint4 st;
        st.x = packbf(e.x, o.x); st.y = packbf(e.y, o.y);
        st.z = packbf(e.z, o.z); st.w = packbf(e.w, o.w);
        *(uint4*)&xsp[kk][p4] = st;
    }
    __syncthreads();

    int lane = tid & 31, wid = tid >> 5;
    int g = lane >> 2, l4 = lane & 3;
    int oc0 = (wid & 3) * 16;
    int pxw = (wid >> 2) * 64;

    #pragma unroll
    for (int p = 0; p < 3; p++) {
        float* op = ((p == 0) ? g_q : (p == 1) ? g_k : g_v) + (size_t)b*C*NPIX + pix0;
        uint32_t Ar[4][4];
        const float* wp0 = w + (size_t)(p*C + oc0 + g)*C;
        const float* wp1 = wp0 + 8*C;
        #pragma unroll
        for (int s = 0; s < 4; s++) {
            float2 e0 = *(const float2*)(wp0 + 16*s + 2*l4);
            float2 e1 = *(const float2*)(wp1 + 16*s + 2*l4);
            float2 e2 = *(const float2*)(wp0 + 16*s + 2*l4 + 8);
            float2 e3 = *(const float2*)(wp1 + 16*s + 2*l4 + 8);
            Ar[s][0] = packbf(e0.x, e0.y);
            Ar[s][1] = packbf(e1.x, e1.y);
            Ar[s][2] = packbf(e2.x, e2.y);
            Ar[s][3] = packbf(e3.x, e3.y);
        }
        float b_lo = bias[p*C + oc0 + g];
        float b_hi = bias[p*C + oc0 + g + 8];

        #pragma unroll
        for (int f = 0; f < 8; f++) {
            int px0f = pxw + f*8;
            float acc[4] = {0.f, 0.f, 0.f, 0.f};
            #pragma unroll
            for (int s = 0; s < 4; s++) {
                uint32_t b0 = xsp[s*8 + l4    ][px0f + g];
                uint32_t b1 = xsp[s*8 + l4 + 4][px0f + g];
                mma_bf16(acc, Ar[s][0], Ar[s][1], Ar[s][2], Ar[s][3], b0, b1);
            }
            float v0 = acc[0] + b_lo, v1 = acc[1] + b_lo;
            float v2 = acc[2] + b_hi, v3 = acc[3] + b_hi;
            if (p < 2) {
                v0 = fmaxf(v0, 0.f); v1 = fmaxf(v1, 0.f);
                v2 = fmaxf(v2, 0.f); v3 = fmaxf(v3, 0.f);
            }
            size_t olo = (size_t)(oc0 + g)*NPIX + px0f + 2*l4;
            *(float2*)&op[olo]          = make_float2(v0, v1);
            *(float2*)&op[olo + 8*NPIX] = make_float2(v2, v3);
        }
    }
}

// ---------------------------------------------------------------
// Single pointwise GEMM 64->64 (bf16 MMA). MODE: 2 = gelu, 3 = +res.
// ---------------------------------------------------------------
template<int MODE>
__global__ __launch_bounds__(256)
void pw_single_kernel(const float* __restrict__ in,
                      const float* __restrict__ w,
                      const float* __restrict__ bias,
                      const float* __restrict__ res,
                      float* __restrict__ out) {
    __shared__ uint32_t xsp[C/2][136];

    int b    = blockIdx.y;
    int pix0 = blockIdx.x * 128;
    int tid  = threadIdx.x;
    const float* inb = in + (size_t)b*C*NPIX + pix0;

    #pragma unroll
    for (int it = 0; it < 4; it++) {
        int idx = tid + it*256;
        int kk = idx >> 5, p4 = (idx & 31) << 2;
        float4 e = *(const float4*)(inb + (size_t)(2*kk    )*NPIX + p4);
        float4 o = *(const float4*)(inb + (size_t)(2*kk + 1)*NPIX + p4);
        uint4 st;
        st.x = packbf(e.x, o.x); st.y = packbf(e.y, o.y);
        st.z = packbf(e.z, o.z); st.w = packbf(e.w, o.w);
        *(uint4*)&xsp[kk][p4] = st;
    }
    __syncthreads();

    int lane = tid & 31, wid = tid >> 5;
    int g = lane >> 2, l4 = lane & 3;
    int oc0 = (wid & 3) * 16;
    int pxw = (wid >> 2) * 64;

    uint32_t Ar[4][4];
    const float* wp0 = w + (size_t)(oc0 + g)*C;
    const float* wp1 = wp0 + 8*C;
    #pragma unroll
    for (int s = 0; s < 4; s++) {
        float2 e0 = *(const float2*)(wp0 + 16*s + 2*l4);
        float2 e1 = *(const float2*)(wp1 + 16*s + 2*l4);
        float2 e2 = *(const float2*)(wp0 + 16*s + 2*l4 + 8);
        float2 e3 = *(const float2*)(wp1 + 16*s + 2*l4 + 8);
        Ar[s][0] = packbf(e0.x, e0.y);
        Ar[s][1] = packbf(e1.x, e1.y);
        Ar[s][2] = packbf(e2.x, e2.y);
        Ar[s][3] = packbf(e3.x, e3.y);
    }
    float b_lo = bias[oc0 + g];
    float b_hi = bias[oc0 + g + 8];
    float* op = out + (size_t)b*C*NPIX + pix0;
    const float* rp = (MODE == 3) ? res + (size_t)b*C*NPIX + pix0 : nullptr;

    #pragma unroll
    for (int f = 0; f < 8; f++) {
        int px0f = pxw + f*8;
        float acc[4] = {0.f, 0.f, 0.f, 0.f};
        #pragma unroll
        for (int s = 0; s < 4; s++) {
            uint32_t b0 = xsp[s*8 + l4    ][px0f + g];
            uint32_t b1 = xsp[s*8 + l4 + 4][px0f + g];
            mma_bf16(acc, Ar[s][0], Ar[s][1], Ar[s][2], Ar[s][3], b0, b1);
        }
        float v0 = acc[0] + b_lo, v1 = acc[1] + b_lo;
        float v2 = acc[2] + b_hi, v3 = acc[3] + b_hi;
        size_t olo = (size_t)(oc0 + g)*NPIX + px0f + 2*l4;
        size_t ohi = olo + 8*NPIX;
        if (MODE == 2) {
            v0 = gelu_exact(v0); v1 = gelu_exact(v1);
            v2 = gelu_exact(v2); v3 = gelu_exact(v3);
        } else {
            v0 += rp[olo]; v1 += rp[olo+1];
            v2 += rp[ohi]; v3 += rp[ohi+1];
        }
        *(float2*)&op[olo] = make_float2(v0, v1);
        *(float2*)&op[ohi] = make_float2(v2, v3);
    }
}

// ---------------------------------------------------------------
// proj 3x3 conv (64->64, pad 1) + bias + residual (bf16 MMA).
// ---------------------------------------------------------------
__global__ __launch_bounds__(256)
void proj3x3_kernel(const float* __restrict__ in,
                    const float* __restrict__ w,
                    const float* __restrict__ bias,
                    const float* __restrict__ res,
                    float* __restrict__ out) {
    __shared__ uint32_t xsp[8][3][136];     // 13 KB

    int b  = blockIdx.y;
    int y  = blockIdx.x >> 1;
    int x0 = (blockIdx.x & 1) << 7;
    int tid = threadIdx.x;
    int lane = tid & 31, wid = tid >> 5;
    int g = lane >> 2, l4 = lane & 3;
    int oc0 = (wid & 3) * 16;
    int pxw = (wid >> 2) * 64;

    const float* inb = in + (size_t)b*C*NPIX;

    float acc[8][4];
    #pragma unroll
    for (int f = 0; f < 8; f++)
        #pragma unroll
        for (int j = 0; j < 4; j++) acc[f][j] = 0.f;

    for (int ic0 = 0; ic0 < C; ic0 += 16) {
        __syncthreads();
        #pragma unroll
        for (int it = 0; it < 3; it++) {
            int idx = tid + it*256;
            int icp = idx / 96, r = idx % 96;
            int dy = r >> 5, q4 = (r & 31) << 2;
            int gy = y + dy - 1;
            float4 e = make_float4(0.f, 0.f, 0.f, 0.f);
            float4 o = make_float4(0.f, 0.f, 0.f, 0.f);
            if (gy >= 0 && gy < HH) {
                e = *(const float4*)(inb + (size_t)(ic0 + 2*icp    )*NPIX + gy*WW + x0 + q4);
                o = *(const float4*)(inb + (size_t)(ic0 + 2*icp + 1)*NPIX + gy*WW + x0 + q4);
            }
            xsp[icp][dy][1 + q4    ] = packbf(e.x, o.x);
            xsp[icp][dy][1 + q4 + 1] = packbf(e.y, o.y);
            xsp[icp][dy][1 + q4 + 2] = packbf(e.z, o.z);
            xsp[icp][dy][1 + q4 + 3] = packbf(e.w, o.w);
        }
        if (tid < 48) {
            int icp = tid / 6, r = tid % 6;
            int dy = r >> 1, side = r & 1;
            int xx = side ? 129 : 0;
            int gy = y + dy - 1;
            int gx = x0 + xx - 1;
            float e = 0.f, o = 0.f;
            if (gy >= 0 && gy < HH && (unsigned)gx < WW) {
                e = inb[(size_t)(ic0 + 2*icp    )*NPIX + gy*WW + gx];
                o = inb[(size_t)(ic0 + 2*icp + 1)*NPIX + gy*WW + gx];
            }
            xsp[icp][dy][xx] = packbf(e, o);
        }
        __syncthreads();

        #pragma unroll
        for (int pp = 0; pp < 9; pp++) {
            int dy = pp / 3, dx = pp % 3;
            const float* wb0 = w + (size_t)(oc0 + g)*(C*9) + pp;
            const float* wb1 = wb0 + (size_t)8*C*9;
            uint32_t a0 = packbf(wb0[(ic0 + 2*l4    )*9], wb0[(ic0 + 2*l4 + 1)*9]);
            uint32_t a1 = packbf(wb1[(ic0 + 2*l4    )*9], wb1[(ic0 + 2*l4 + 1)*9]);
            uint32_t a2 = packbf(wb0[(ic0 + 2*l4 + 8)*9], wb0[(ic0 + 2*l4 + 9)*9]);
            uint32_t a3 = packbf(wb1[(ic0 + 2*l4 + 8)*9], wb1[(ic0 + 2*l4 + 9)*9]);
            #pragma unroll
            for (int f = 0; f < 8; f++) {
                int xb = pxw + f*8 + g + dx;
                uint32_t b0 = xsp[l4    ][dy][xb];
                uint32_t b1 = xsp[l4 + 4][dy][xb];
                mma_bf16(acc[f], a0, a1, a2, a3, b0, b1);
            }
        }
    }

    float b_lo = bias[oc0 + g];
    float b_hi = bias[oc0 + g + 8];
    size_t pbase = (size_t)b*C*NPIX + (size_t)y*WW + x0;
    #pragma unroll
    for (int f = 0; f < 8; f++) {
        int px = pxw + f*8 + 2*l4;
        size_t olo = pbase + (size_t)(oc0 + g)*NPIX + px;
        size_t ohi = olo + 8*NPIX;
        float v0 = acc[f][0] + b_lo + res[olo];
        float v1 = acc[f][1] + b_lo + res[olo+1];
        float v2 = acc[f][2] + b_hi + res[ohi];
        float v3 = acc[f][3] + b_hi + res[ohi+1];
        *(float2*)&out[olo] = make_float2(v0, v1);
        *(float2*)&out[ohi] = make_float2(v2, v3);
    }
}

// ---------------------------------------------------------------
// kv[b,h,d,e] = sum_n k_unfold[d,n] * v[e,n]  ;  ksum[b,h,d]
// ---------------------------------------------------------------
#define KV_ROWS 16
__global__ __launch_bounds__(256)
void kv_kernel() {
    int bh = blockIdx.y;
    int b  = bh >> 3;
    int h  = bh & 7;
    int warp = threadIdx.x >> 5;
    int lane = threadIdx.x & 31;
    int cl = warp;

    const float* kc = g_k + ((size_t)(b*C + 8*h + cl))*NPIX;
    const float* vb = g_v + ((size_t)(b*C + 8*h))*NPIX;

    float acc[9][8];
    float accs[9];
    #pragma unroll
    for (int p = 0; p < 9; p++) {
        accs[p] = 0.0f;
        #pragma unroll
        for (int e = 0; e < 8; e++) acc[p][e] = 0.0f;
    }

    int y0 = blockIdx.x * KV_ROWS;
    for (int y = y0; y < y0 + KV_ROWS; y++) {
        #pragma unroll 1
        for (int xi = 0; xi < 8; xi++) {
            int xx0 = lane + 32*xi;
            float vv[8];
            #pragma unroll
            for (int e = 0; e < 8; e++) vv[e] = vb[e*NPIX + y*WW + xx0];
            #pragma unroll
            for (int i = 0; i < 3; i++) {
                int yy = y + i - 1;
                if (yy < 0 || yy >= HH) continue;
                #pragma unroll
                for (int j = 0; j < 3; j++) {
                    int xj = xx0 + j - 1;
                    if (xj < 0 || xj >= WW) continue;
                    float kl = kc[yy*WW + xj];
                    int pp = i*3 + j;
                    accs[pp] += kl;
                    #pragma unroll
                    for (int e = 0; e < 8; e++)
                        acc[pp][e] = fmaf(kl, vv[e], acc[pp][e]);
                }
            }
        }
    }

    #pragma unroll
    for (int pp = 0; pp < 9; pp++) {
        #pragma unroll
        for (int e = 0; e < 8; e++) {
            float v = acc[pp][e];
            for (int s = 16; s > 0; s >>= 1) v += __shfl_xor_sync(0xffffffffu, v, s);
            acc[pp][e] = v;
        }
        float v = accs[pp];
        for (int s = 16; s > 0; s >>= 1) v += __shfl_xor_sync(0xffffffffu, v, s);
        accs[pp] = v;
    }

    if (lane == 0) {
        float* outp = g_kv + bh*KVSZ;
        #pragma unroll
        for (int pp = 0; pp < 9; pp++) {
            int d = cl*9 + pp;
            #pragma unroll
            for (int e = 0; e < 8; e++) atomicAdd(&outp[d*8 + e], acc[pp][e]);
            atomicAdd(&outp[576 + d], accs[pp]);
        }
    }
}

// ---------------------------------------------------------------
// Attention readout as bf16 MMA 3x3 "conv" with data-dependent weights.
// Per (b,h): out rows m=0..7 -> num[e], m=8 -> den; K axis pp-major
// (d = pp*8+cl, padded 72->80 = 5 k16 steps).
// Block: one head, 4 output rows x 128 px. grid (128, 8, BATCH).
// xsp[kk][j][140]: channel-pairs (2kk,2kk+1) bf16x2, row j = y0+j-1,
// interior px p at [4+p], halo at [3] and [132].
// ---------------------------------------------------------------
__global__ __launch_bounds__(256)
void attn_kernel() {
    __shared__ __align__(16) uint32_t xsp[4][6][140];   // 13.4 KB

    int b  = blockIdx.z;
    int h  = blockIdx.y;
    int y0 = (blockIdx.x >> 1) * 4;
    int x0 = (blockIdx.x & 1) << 7;
    int tid = threadIdx.x;
    int lane = tid & 31, wid = tid >> 5;
    int g = lane >> 2, l4 = lane & 3;
    int r  = wid >> 1;                  // output row within block (0..3)
    int xh = wid & 1;                   // x sub-half (64 px)

    const float* qbh = g_q + ((size_t)(b*C + 8*h))*NPIX;

    // ---- fill q patch: 4 ch-pairs x 6 rows x 128 interior px ----
    #pragma unroll
    for (int it = 0; it < 3; it++) {
        int idx = tid + it*256;         // 0..767
        int kk = idx / 192;
        int rr = idx % 192;
        int j  = rr >> 5;               // 0..5
        int q4 = (rr & 31) << 2;        // 0..124
        int gy = y0 + j - 1;
        float4 e = make_float4(0.f, 0.f, 0.f, 0.f);
        float4 o = make_float4(0.f, 0.f, 0.f, 0.f);
        if (gy >= 0 && gy < HH) {
            e = *(const float4*)(qbh + (size_t)(2*kk    )*NPIX + gy*WW + x0 + q4);
            o = *(const float4*)(qbh + (size_t)(2*kk + 1)*NPIX + gy*WW + x0 + q4);
        }
        uint4 st;
        st.x = packbf(e.x, o.x); st.y = packbf(e.y, o.y);
        st.z = packbf(e.z, o.z); st.w = packbf(e.w, o.w);
        *(uint4*)&xsp[kk][j][4 + q4] = st;
    }
    // halo: 4 kk x 6 j x 2 sides
    if (tid < 48) {
        int kk = tid / 12, rr = tid % 12;
        int j = rr >> 1, side = rr & 1;
        int gy = y0 + j - 1;
        int gx = side ? (x0 + 128) : (x0 - 1);
        float e = 0.f, o = 0.f;
        if (gy >= 0 && gy < HH && (unsigned)gx < WW) {
            e = qbh[(size_t)(2*kk    )*NPIX + gy*WW + gx];
            o = qbh[(size_t)(2*kk + 1)*NPIX + gy*WW + gx];
        }
        xsp[kk][j][side ? 132 : 3] = packbf(e, o);
    }

    // ---- A frags from g_kv (5 ksteps; kstep s covers pp=2s, 2s+1) ----
    const float* kvb = g_kv + (size_t)(b*HEADS + h)*KVSZ;
    uint32_t Ar[5][4];
    #pragma unroll
    for (int s = 0; s < 5; s++) {
        int ppa = 2*s;
        Ar[s][0] = packbf(kvb[((2*l4    )*9 + ppa)*8 + g],
                          kvb[((2*l4 + 1)*9 + ppa)*8 + g]);
        Ar[s][1] = (g == 0) ? packbf(kvb[576 + (2*l4)*9 + ppa],
                                     kvb[576 + (2*l4 + 1)*9 + ppa]) : 0u;
        if (s < 4) {
            int ppb = ppa + 1;
            Ar[s][2] = packbf(kvb[((2*l4    )*9 + ppb)*8 + g],
                              kvb[((2*l4 + 1)*9 + ppb)*8 + g]);
            Ar[s][3] = (g == 0) ? packbf(kvb[576 + (2*l4)*9 + ppb],
                                         kvb[576 + (2*l4 + 1)*9 + ppb]) : 0u;
        } else {
            Ar[s][2] = 0u; Ar[s][3] = 0u;
        }
    }
    __syncthreads();

    // ---- MMA + divide + store ----
    #pragma unroll
    for (int f = 0; f < 8; f++) {
        int nb = xh*64 + f*8 + g;       // local px of B column
        float acc[4] = {0.f, 0.f, 0.f, 0.f};
        #pragma unroll
        for (int s = 0; s < 5; s++) {
            int ppa = 2*s;
            int dya = ppa / 3, dxa = ppa % 3;
            uint32_t b0 = xsp[l4][r + dya][3 + nb + dxa];
            uint32_t b1 = b0;
            if (s < 4) {
                int ppb = ppa + 1;
                b1 = xsp[l4][r + ppb/3][3 + nb + ppb%3];
            }
            mma_bf16(acc, Ar[s][0], Ar[s][1], Ar[s][2], Ar[s][3], b0, b1);
        }
        float den0 = __shfl_sync(0xffffffffu, acc[2], l4);
        float den1 = __shfl_sync(0xffffffffu, acc[3], l4);
        float i0 = 1.0f / (den0 + 1e-6f);
        float i1 = 1.0f / (den1 + 1e-6f);
        size_t on = (size_t)(b*C + 8*h + g)*NPIX
                  + (size_t)(y0 + r)*WW + x0 + xh*64 + f*8 + 2*l4;
        *(float2*)&g_o[on] = make_float2(acc[0]*i0, acc[1]*i1);
    }
}

// ---------------------------------------------------------------
// depthwise 3x3 conv (pad 1) + bias + exact GELU; 4 px/thread.
// ---------------------------------------------------------------
__global__ __launch_bounds__(256)
void dw_gelu_kernel(const float* __restrict__ in,
                    const float* __restrict__ w,
                    const float* __restrict__ bias,
                    float* __restrict__ out) {
    int idx = blockIdx.x * 256 + threadIdx.x;
    int n   = idx * 4;
    int x   = n & 255;
    int y   = (n >> 8) & 255;
    int bc  = n >> 16;
    int c   = bc & (C - 1);
    const float* ib = in + (size_t)bc*NPIX;

    float bv = bias[c];
    float a[4] = {bv, bv, bv, bv};
    #pragma unroll
    for (int i = 0; i < 3; i++) {
        int yy = y + i - 1;
        if (yy < 0 || yy >= HH) continue;
        const float* r = ib + yy*WW;
        float row[6];
        row[0] = (x > 0) ? r[x-1] : 0.f;
        float4 m = *(const float4*)&r[x];
        row[1] = m.x; row[2] = m.y; row[3] = m.z; row[4] = m.w;
        row[5] = (x + 4 < WW) ? r[x+4] : 0.f;
        #pragma unroll
        for (int j = 0; j < 3; j++) {
            float wv = w[c*9 + i*3 + j];
            #pragma unroll
            for (int t = 0; t < 4; t++)
                a[t] = fmaf(wv, row[t + j], a[t]);
        }
    }
    float4 o = make_float4(gelu_exact(a[0]), gelu_exact(a[1]),
                           gelu_exact(a[2]), gelu_exact(a[3]));
    *(float4*)&out[(size_t)n] = o;
}

// ---------------------------------------------------------------
extern "C" void kernel_launch(void* const* d_in, const int* in_sizes, int n_in,
                              void* d_out, int out_size) {
    const float* x      = (const float*)d_in[0];
    const float* qkv_w  = (const float*)d_in[1];
    const float* qkv_b  = (const float*)d_in[2];
    const float* proj_w = (const float*)d_in[3];
    const float* proj_b = (const float*)d_in[4];
    const float* ffn1_w = (const float*)d_in[5];
    const float* ffn1_b = (const float*)d_in[6];
    const float* dw_w   = (const float*)d_in[7];
    const float* dw_b   = (const float*)d_in[8];
    const float* ffn2_w = (const float*)d_in[9];
    const float* ffn2_b = (const float*)d_in[10];
    float* out = (float*)d_out;

    float *p_o, *p_x1, *p_h1, *p_h2;
    cudaGetSymbolAddress((void**)&p_o,  g_o);
    cudaGetSymbolAddress((void**)&p_x1, g_x1);
    cudaGetSymbolAddress((void**)&p_h1, g_h1);
    cudaGetSymbolAddress((void**)&p_h2, g_h2);

    dim3 gpw(NPIX/128, BATCH);     // (512, 2)

    zero_kv_kernel<<<(BATCH*HEADS*KVSZ + 255)/256, 256>>>();
    pw_qkv_kernel<<<gpw, 256>>>(x, qkv_w, qkv_b);
    kv_kernel<<<dim3(HH/KV_ROWS, BATCH*HEADS), 256>>>();
    attn_kernel<<<dim3(128, HEADS, BATCH), 256>>>();
    proj3x3_kernel<<<gpw, 256>>>(p_o, proj_w, proj_b, x, p_x1);
    pw_single_kernel<2><<<gpw, 256>>>(p_x1, ffn1_w, ffn1_b, nullptr, p_h1);
    dw_gelu_kernel<<<BATCH*C*NPIX/1024, 256>>>(p_h1, dw_w, dw_b, p_h2);
    pw_single_kernel<3><<<gpw, 256>>>(p_h2, ffn2_w, ffn2_b, p_x1, out);
}

// round 14
// speedup vs baseline: 2.5546x; 1.0695x over previous
#include <cuda_runtime.h>
#include <cuda_bf16.h>
#include <math.h>
#include <stdint.h>

#define C        64
#define HH       256
#define WW       256
#define NPIX     65536            // HH*WW
#define BATCH    2
#define HEADS    8
#define KVSZ     648              // 72*8 + 72 per (b,h)

// -------- scratch (device globals) --------
// bf16 activations (GEMM operands); fp32 residual spine (x1) + kv stats.
__device__ __nv_bfloat16 g_q [BATCH*C*NPIX];
__device__ __nv_bfloat16 g_k [BATCH*C*NPIX];
__device__ __nv_bfloat16 g_v [BATCH*C*NPIX];
__device__ __nv_bfloat16 g_o [BATCH*C*NPIX];
__device__ __nv_bfloat16 g_h1[BATCH*C*NPIX];
__device__ __nv_bfloat16 g_h2[BATCH*C*NPIX];
__device__ float g_x1[BATCH*C*NPIX];
__device__ float g_kv[BATCH*HEADS*KVSZ];

__device__ __forceinline__ float gelu_exact(float v) {
    return 0.5f * v * (1.0f + erff(v * 0.7071067811865476f));
}

__device__ __forceinline__ uint32_t packbf(float lo, float hi) {
    __nv_bfloat162 t = __floats2bfloat162_rn(lo, hi);   // .x = lo (low 16b)
    return *reinterpret_cast<uint32_t*>(&t);
}

// m16n8k16 bf16 MMA, fp32 accum. (fragment mapping as before)
__device__ __forceinline__ void mma_bf16(float* c,
        uint32_t a0, uint32_t a1, uint32_t a2, uint32_t a3,
        uint32_t b0, uint32_t b1) {
    asm volatile(
        "mma.sync.aligned.m16n8k16.row.col.f32.bf16.bf16.f32 "
        "{%0,%1,%2,%3}, {%4,%5,%6,%7}, {%8,%9}, {%0,%1,%2,%3};\n"
        : "+f"(c[0]), "+f"(c[1]), "+f"(c[2]), "+f"(c[3])
        : "r"(a0), "r"(a1), "r"(a2), "r"(a3), "r"(b0), "r"(b1));
}

// interleave bf16 pairs: (e0,o0) and (e1,o1) from two bf16x2 words
#define PRMT_LO 0x5410u
#define PRMT_HI 0x7632u

// ---------------------------------------------------------------
__global__ void zero_kv_kernel() {
    int i = blockIdx.x * blockDim.x + threadIdx.x;
    if (i < BATCH*HEADS*KVSZ) g_kv[i] = 0.0f;
}

// ---------------------------------------------------------------
// Fused qkv pointwise GEMM (bf16 MMA): fp32 x in, bf16 q/k/v out.
// ---------------------------------------------------------------
__global__ __launch_bounds__(256)
void pw_qkv_kernel(const float* __restrict__ x,
                   const float* __restrict__ w,
                   const float* __restrict__ bias) {
    __shared__ uint32_t xsp[C/2][136];      // 17.4 KB

    int b    = blockIdx.y;
    int pix0 = blockIdx.x * 128;
    int tid  = threadIdx.x;
    const float* inb = x + (size_t)b*C*NPIX + pix0;

    #pragma unroll
    for (int it = 0; it < 4; it++) {
        int idx = tid + it*256;             // 0..1023
        int kk = idx >> 5, p4 = (idx & 31) << 2;
        float4 e = *(const float4*)(inb + (size_t)(2*kk    )*NPIX + p4);
        float4 o = *(const float4*)(inb + (size_t)(2*kk + 1)*NPIX + p4);
        uint4 st;
        st.x = packbf(e.x, o.x); st.y = packbf(e.y, o.y);
        st.z = packbf(e.z, o.z); st.w = packbf(e.w, o.w);
        *(uint4*)&xsp[kk][p4] = st;
    }
    __syncthreads();

    int lane = tid & 31, wid = tid >> 5;
    int g = lane >> 2, l4 = lane & 3;
    int oc0 = (wid & 3) * 16;
    int pxw = (wid >> 2) * 64;

    #pragma unroll
    for (int p = 0; p < 3; p++) {
        __nv_bfloat16* op = ((p == 0) ? g_q : (p == 1) ? g_k : g_v)
                          + (size_t)b*C*NPIX + pix0;
        uint32_t Ar[4][4];
        const float* wp0 = w + (size_t)(p*C + oc0 + g)*C;
        const float* wp1 = wp0 + 8*C;
        #pragma unroll
        for (int s = 0; s < 4; s++) {
            float2 e0 = *(const float2*)(wp0 + 16*s + 2*l4);
            float2 e1 = *(const float2*)(wp1 + 16*s + 2*l4);
            float2 e2 = *(const float2*)(wp0 + 16*s + 2*l4 + 8);
            float2 e3 = *(const float2*)(wp1 + 16*s + 2*l4 + 8);
            Ar[s][0] = packbf(e0.x, e0.y);
            Ar[s][1] = packbf(e1.x, e1.y);
            Ar[s][2] = packbf(e2.x, e2.y);
            Ar[s][3] = packbf(e3.x, e3.y);
        }
        float b_lo = bias[p*C + oc0 + g];
        float b_hi = bias[p*C + oc0 + g + 8];

        #pragma unroll
        for (int f = 0; f < 8; f++) {
            int px0f = pxw + f*8;
            float acc[4] = {0.f, 0.f, 0.f, 0.f};
            #pragma unroll
            for (int s = 0; s < 4; s++) {
                uint32_t b0 = xsp[s*8 + l4    ][px0f + g];
                uint32_t b1 = xsp[s*8 + l4 + 4][px0f + g];
                mma_bf16(acc, Ar[s][0], Ar[s][1], Ar[s][2], Ar[s][3], b0, b1);
            }
            float v0 = acc[0] + b_lo, v1 = acc[1] + b_lo;
            float v2 = acc[2] + b_hi, v3 = acc[3] + b_hi;
            if (p < 2) {
                v0 = fmaxf(v0, 0.f); v1 = fmaxf(v1, 0.f);
                v2 = fmaxf(v2, 0.f); v3 = fmaxf(v3, 0.f);
            }
            size_t olo = (size_t)(oc0 + g)*NPIX + px0f + 2*l4;
            *(uint32_t*)&op[olo]          = packbf(v0, v1);
            *(uint32_t*)&op[olo + 8*NPIX] = packbf(v2, v3);
        }
    }
}

// ---------------------------------------------------------------
// ffn1: fp32 x1 in -> gelu -> bf16 h1 out  (bf16 MMA)
// ---------------------------------------------------------------
__global__ __launch_bounds__(256)
void pw_gelu_kernel(const float* __restrict__ in,
                    const float* __restrict__ w,
                    const float* __restrict__ bias,
                    __nv_bfloat16* __restrict__ out) {
    __shared__ uint32_t xsp[C/2][136];

    int b    = blockIdx.y;
    int pix0 = blockIdx.x * 128;
    int tid  = threadIdx.x;
    const float* inb = in + (size_t)b*C*NPIX + pix0;

    #pragma unroll
    for (int it = 0; it < 4; it++) {
        int idx = tid + it*256;
        int kk = idx >> 5, p4 = (idx & 31) << 2;
        float4 e = *(const float4*)(inb + (size_t)(2*kk    )*NPIX + p4);
        float4 o = *(const float4*)(inb + (size_t)(2*kk + 1)*NPIX + p4);
        uint4 st;
        st.x = packbf(e.x, o.x); st.y = packbf(e.y, o.y);
        st.z = packbf(e.z, o.z); st.w = packbf(e.w, o.w);
        *(uint4*)&xsp[kk][p4] = st;
    }
    __syncthreads();

    int lane = tid & 31, wid = tid >> 5;
    int g = lane >> 2, l4 = lane & 3;
    int oc0 = (wid & 3) * 16;
    int pxw = (wid >> 2) * 64;

    uint32_t Ar[4][4];
    const float* wp0 = w + (size_t)(oc0 + g)*C;
    const float* wp1 = wp0 + 8*C;
    #pragma unroll
    for (int s = 0; s < 4; s++) {
        float2 e0 = *(const float2*)(wp0 + 16*s + 2*l4);
        float2 e1 = *(const float2*)(wp1 + 16*s + 2*l4);
        float2 e2 = *(const float2*)(wp0 + 16*s + 2*l4 + 8);
        float2 e3 = *(const float2*)(wp1 + 16*s + 2*l4 + 8);
        Ar[s][0] = packbf(e0.x, e0.y);
        Ar[s][1] = packbf(e1.x, e1.y);
        Ar[s][2] = packbf(e2.x, e2.y);
        Ar[s][3] = packbf(e3.x, e3.y);
    }
    float b_lo = bias[oc0 + g];
    float b_hi = bias[oc0 + g + 8];
    __nv_bfloat16* op = out + (size_t)b*C*NPIX + pix0;

    #pragma unroll
    for (int f = 0; f < 8; f++) {
        int px0f = pxw + f*8;
        float acc[4] = {0.f, 0.f, 0.f, 0.f};
        #pragma unroll
        for (int s = 0; s < 4; s++) {
            uint32_t b0 = xsp[s*8 + l4    ][px0f + g];
            uint32_t b1 = xsp[s*8 + l4 + 4][px0f + g];
            mma_bf16(acc, Ar[s][0], Ar[s][1], Ar[s][2], Ar[s][3], b0, b1);
        }
        float v0 = gelu_exact(acc[0] + b_lo);
        float v1 = gelu_exact(acc[1] + b_lo);
        float v2 = gelu_exact(acc[2] + b_hi);
        float v3 = gelu_exact(acc[3] + b_hi);
        size_t olo = (size_t)(oc0 + g)*NPIX + px0f + 2*l4;
        *(uint32_t*)&op[olo]          = packbf(v0, v1);
        *(uint32_t*)&op[olo + 8*NPIX] = packbf(v2, v3);
    }
}

// ---------------------------------------------------------------
// ffn2: bf16 h2 in + fp32 res -> fp32 out  (bf16 MMA)
// ---------------------------------------------------------------
__global__ __launch_bounds__(256)
void pw_res_kernel(const __nv_bfloat16* __restrict__ in,
                   const float* __restrict__ w,
                   const float* __restrict__ bias,
                   const float* __restrict__ res,
                   float* __restrict__ out) {
    __shared__ uint32_t xsp[C/2][136];

    int b    = blockIdx.y;
    int pix0 = blockIdx.x * 128;
    int tid  = threadIdx.x;
    const __nv_bfloat16* inb = in + (size_t)b*C*NPIX + pix0;

    #pragma unroll
    for (int it = 0; it < 2; it++) {
        int idx = tid + it*256;             // 0..511 = 32 kk x 16 octets
        int kk = idx >> 4, q8 = (idx & 15) << 3;
        uint4 e8 = *(const uint4*)(inb + (size_t)(2*kk    )*NPIX + q8);
        uint4 o8 = *(const uint4*)(inb + (size_t)(2*kk + 1)*NPIX + q8);
        uint4 s0, s1;
        s0.x = __byte_perm(e8.x, o8.x, PRMT_LO); s0.y = __byte_perm(e8.x, o8.x, PRMT_HI);
        s0.z = __byte_perm(e8.y, o8.y, PRMT_LO); s0.w = __byte_perm(e8.y, o8.y, PRMT_HI);
        s1.x = __byte_perm(e8.z, o8.z, PRMT_LO); s1.y = __byte_perm(e8.z, o8.z, PRMT_HI);
        s1.z = __byte_perm(e8.w, o8.w, PRMT_LO); s1.w = __byte_perm(e8.w, o8.w, PRMT_HI);
        *(uint4*)&xsp[kk][q8]     = s0;
        *(uint4*)&xsp[kk][q8 + 4] = s1;
    }
    __syncthreads();

    int lane = tid & 31, wid = tid >> 5;
    int g = lane >> 2, l4 = lane & 3;
    int oc0 = (wid & 3) * 16;
    int pxw = (wid >> 2) * 64;

    uint32_t Ar[4][4];
    const float* wp0 = w + (size_t)(oc0 + g)*C;
    const float* wp1 = wp0 + 8*C;
    #pragma unroll
    for (int s = 0; s < 4; s++) {
        float2 e0 = *(const float2*)(wp0 + 16*s + 2*l4);
        float2 e1 = *(const float2*)(wp1 + 16*s + 2*l4);
        float2 e2 = *(const float2*)(wp0 + 16*s + 2*l4 + 8);
        float2 e3 = *(const float2*)(wp1 + 16*s + 2*l4 + 8);
        Ar[s][0] = packbf(e0.x, e0.y);
        Ar[s][1] = packbf(e1.x, e1.y);
        Ar[s][2] = packbf(e2.x, e2.y);
        Ar[s][3] = packbf(e3.x, e3.y);
    }
    float b_lo = bias[oc0 + g];
    float b_hi = bias[oc0 + g + 8];
    float* op = out + (size_t)b*C*NPIX + pix0;
    const float* rp = res + (size_t)b*C*NPIX + pix0;

    #pragma unroll
    for (int f = 0; f < 8; f++) {
        int px0f = pxw + f*8;
        float acc[4] = {0.f, 0.f, 0.f, 0.f};
        #pragma unroll
        for (int s = 0; s < 4; s++) {
            uint32_t b0 = xsp[s*8 + l4    ][px0f + g];
            uint32_t b1 = xsp[s*8 + l4 + 4][px0f + g];
            mma_bf16(acc, Ar[s][0], Ar[s][1], Ar[s][2], Ar[s][3], b0, b1);
        }
        size_t olo = (size_t)(oc0 + g)*NPIX + px0f + 2*l4;
        size_t ohi = olo + 8*NPIX;
        float v0 = acc[0] + b_lo + rp[olo];
        float v1 = acc[1] + b_lo + rp[olo+1];
        float v2 = acc[2] + b_hi + rp[ohi];
        float v3 = acc[3] + b_hi + rp[ohi+1];
        *(float2*)&op[olo] = make_float2(v0, v1);
        *(float2*)&op[ohi] = make_float2(v2, v3);
    }
}

// ---------------------------------------------------------------
// proj 3x3 conv (bf16 o in, fp32 res/out): x1 = x + proj(o)
// xsp[8][3][136]: interior px p at [4+p], halo at [3]/[132].
// ---------------------------------------------------------------
__global__ __launch_bounds__(256)
void proj3x3_kernel(const __nv_bfloat16* __restrict__ in,
                    const float* __restrict__ w,
                    const float* __restrict__ bias,
                    const float* __restrict__ res,
                    float* __restrict__ out) {
    __shared__ uint32_t xsp[8][3][136];     // 13 KB

    int b  = blockIdx.y;
    int y  = blockIdx.x >> 1;
    int x0 = (blockIdx.x & 1) << 7;
    int tid = threadIdx.x;
    int lane = tid & 31, wid = tid >> 5;
    int g = lane >> 2, l4 = lane & 3;
    int oc0 = (wid & 3) * 16;
    int pxw = (wid >> 2) * 64;

    const __nv_bfloat16* inb = in + (size_t)b*C*NPIX;

    float acc[8][4];
    #pragma unroll
    for (int f = 0; f < 8; f++)
        #pragma unroll
        for (int j = 0; j < 4; j++) acc[f][j] = 0.f;

    for (int ic0 = 0; ic0 < C; ic0 += 16) {
        __syncthreads();
        // interior: 8 icp x 3 dy x 16 octets = 384 items
        #pragma unroll
        for (int it = 0; it < 2; it++) {
            int idx = tid + it*256;
            if (idx < 384) {
                int icp = idx / 48;
                int rr  = idx % 48;
                int dy  = rr / 16;
                int q8  = (rr & 15) << 3;
                int gy = y + dy - 1;
                uint4 e8 = make_uint4(0,0,0,0), o8 = make_uint4(0,0,0,0);
                if (gy >= 0 && gy < HH) {
                    e8 = *(const uint4*)(inb + (size_t)(ic0 + 2*icp    )*NPIX + gy*WW + x0 + q8);
                    o8 = *(const uint4*)(inb + (size_t)(ic0 + 2*icp + 1)*NPIX + gy*WW + x0 + q8);
                }
                uint4 s0, s1;
                s0.x = __byte_perm(e8.x, o8.x, PRMT_LO); s0.y = __byte_perm(e8.x, o8.x, PRMT_HI);
                s0.z = __byte_perm(e8.y, o8.y, PRMT_LO); s0.w = __byte_perm(e8.y, o8.y, PRMT_HI);
                s1.x = __byte_perm(e8.z, o8.z, PRMT_LO); s1.y = __byte_perm(e8.z, o8.z, PRMT_HI);
                s1.z = __byte_perm(e8.w, o8.w, PRMT_LO); s1.w = __byte_perm(e8.w, o8.w, PRMT_HI);
                *(uint4*)&xsp[icp][dy][4 + q8]     = s0;
                *(uint4*)&xsp[icp][dy][4 + q8 + 4] = s1;
            }
        }
        // halo
        if (tid < 48) {
            int icp = tid / 6, r = tid % 6;
            int dy = r >> 1, side = r & 1;
            int gy = y + dy - 1;
            int gx = side ? (x0 + 128) : (x0 - 1);
            uint32_t wd = 0;
            if (gy >= 0 && gy < HH && (unsigned)gx < WW) {
                uint16_t eb = *reinterpret_cast<const uint16_t*>(inb + (size_t)(ic0 + 2*icp    )*NPIX + gy*WW + gx);
                uint16_t ob = *reinterpret_cast<const uint16_t*>(inb + (size_t)(ic0 + 2*icp + 1)*NPIX + gy*WW + gx);
                wd = (uint32_t)eb | ((uint32_t)ob << 16);
            }
            xsp[icp][dy][side ? 132 : 3] = wd;
        }
        __syncthreads();

        #pragma unroll
        for (int pp = 0; pp < 9; pp++) {
            int dy = pp / 3, dx = pp % 3;
            const float* wb0 = w + (size_t)(oc0 + g)*(C*9) + pp;
            const float* wb1 = wb0 + (size_t)8*C*9;
            uint32_t a0 = packbf(wb0[(ic0 + 2*l4    )*9], wb0[(ic0 + 2*l4 + 1)*9]);
            uint32_t a1 = packbf(wb1[(ic0 + 2*l4    )*9], wb1[(ic0 + 2*l4 + 1)*9]);
            uint32_t a2 = packbf(wb0[(ic0 + 2*l4 + 8)*9], wb0[(ic0 + 2*l4 + 9)*9]);
            uint32_t a3 = packbf(wb1[(ic0 + 2*l4 + 8)*9], wb1[(ic0 + 2*l4 + 9)*9]);
            #pragma unroll
            for (int f = 0; f < 8; f++) {
                int xb = 3 + pxw + f*8 + g + dx;
                uint32_t b0 = xsp[l4    ][dy][xb];
                uint32_t b1 = xsp[l4 + 4][dy][xb];
                mma_bf16(acc[f], a0, a1, a2, a3, b0, b1);
            }
        }
    }

    float b_lo = bias[oc0 + g];
    float b_hi = bias[oc0 + g + 8];
    size_t pbase = (size_t)b*C*NPIX + (size_t)y*WW + x0;
    #pragma unroll
    for (int f = 0; f < 8; f++) {
        int px = pxw + f*8 + 2*l4;
        size_t olo = pbase + (size_t)(oc0 + g)*NPIX + px;
        size_t ohi = olo + 8*NPIX;
        float v0 = acc[f][0] + b_lo + res[olo];
        float v1 = acc[f][1] + b_lo + res[olo+1];
        float v2 = acc[f][2] + b_hi + res[ohi];
        float v3 = acc[f][3] + b_hi + res[ohi+1];
        *(float2*)&out[olo] = make_float2(v0, v1);
        *(float2*)&out[ohi] = make_float2(v2, v3);
    }
}

// ---------------------------------------------------------------
// kv[b,h,d,e] = sum_n k_unfold[d,n] * v[e,n]  ;  ksum[b,h,d]  (bf16 in)
// ---------------------------------------------------------------
#define KV_ROWS 16
__global__ __launch_bounds__(256)
void kv_kernel() {
    int bh = blockIdx.y;
    int b  = bh >> 3;
    int h  = bh & 7;
    int warp = threadIdx.x >> 5;
    int lane = threadIdx.x & 31;
    int cl = warp;

    const __nv_bfloat16* kc = g_k + ((size_t)(b*C + 8*h + cl))*NPIX;
    const __nv_bfloat16* vb = g_v + ((size_t)(b*C + 8*h))*NPIX;

    float acc[9][8];
    float accs[9];
    #pragma unroll
    for (int p = 0; p < 9; p++) {
        accs[p] = 0.0f;
        #pragma unroll
        for (int e = 0; e < 8; e++) acc[p][e] = 0.0f;
    }

    int y0 = blockIdx.x * KV_ROWS;
    for (int y = y0; y < y0 + KV_ROWS; y++) {
        #pragma unroll 1
        for (int xi = 0; xi < 8; xi++) {
            int xx0 = lane + 32*xi;
            float vv[8];
            #pragma unroll
            for (int e = 0; e < 8; e++)
                vv[e] = __bfloat162float(vb[e*NPIX + y*WW + xx0]);
            #pragma unroll
            for (int i = 0; i < 3; i++) {
                int yy = y + i - 1;
                if (yy < 0 || yy >= HH) continue;
                #pragma unroll
                for (int j = 0; j < 3; j++) {
                    int xj = xx0 + j - 1;
                    if (xj < 0 || xj >= WW) continue;
                    float kl = __bfloat162float(kc[yy*WW + xj]);
                    int pp = i*3 + j;
                    accs[pp] += kl;
                    #pragma unroll
                    for (int e = 0; e < 8; e++)
                        acc[pp][e] = fmaf(kl, vv[e], acc[pp][e]);
                }
            }
        }
    }

    #pragma unroll
    for (int pp = 0; pp < 9; pp++) {
        #pragma unroll
        for (int e = 0; e < 8; e++) {
            float v = acc[pp][e];
            for (int s = 16; s > 0; s >>= 1) v += __shfl_xor_sync(0xffffffffu, v, s);
            acc[pp][e] = v;
        }
        float v = accs[pp];
        for (int s = 16; s > 0; s >>= 1) v += __shfl_xor_sync(0xffffffffu, v, s);
        accs[pp] = v;
    }

    if (lane == 0) {
        float* outp = g_kv + bh*KVSZ;
        #pragma unroll
        for (int pp = 0; pp < 9; pp++) {
            int d = cl*9 + pp;
            #pragma unroll
            for (int e = 0; e < 8; e++) atomicAdd(&outp[d*8 + e], acc[pp][e]);
            atomicAdd(&outp[576 + d], accs[pp]);
        }
    }
}

// ---------------------------------------------------------------
// Attention readout as bf16 MMA 3x3 conv (q bf16 in, o bf16 out).
// ---------------------------------------------------------------
__global__ __launch_bounds__(256)
void attn_kernel() {
    __shared__ __align__(16) uint32_t xsp[4][6][140];   // 13.4 KB

    int b  = blockIdx.z;
    int h  = blockIdx.y;
    int y0 = (blockIdx.x >> 1) * 4;
    int x0 = (blockIdx.x & 1) << 7;
    int tid = threadIdx.x;
    int lane = tid & 31, wid = tid >> 5;
    int g = lane >> 2, l4 = lane & 3;
    int r  = wid >> 1;
    int xh = wid & 1;

    const __nv_bfloat16* qbh = g_q + ((size_t)(b*C + 8*h))*NPIX;

    // fill: 4 kk x 6 rows x 16 octets = 384 items
    #pragma unroll
    for (int it = 0; it < 2; it++) {
        int idx = tid + it*256;
        if (idx < 384) {
            int kk = idx / 96;
            int rr = idx % 96;
            int j  = rr / 16;
            int q8 = (rr & 15) << 3;
            int gy = y0 + j - 1;
            uint4 e8 = make_uint4(0,0,0,0), o8 = make_uint4(0,0,0,0);
            if (gy >= 0 && gy < HH) {
                e8 = *(const uint4*)(qbh + (size_t)(2*kk    )*NPIX + gy*WW + x0 + q8);
                o8 = *(const uint4*)(qbh + (size_t)(2*kk + 1)*NPIX + gy*WW + x0 + q8);
            }
            uint4 s0, s1;
            s0.x = __byte_perm(e8.x, o8.x, PRMT_LO); s0.y = __byte_perm(e8.x, o8.x, PRMT_HI);
            s0.z = __byte_perm(e8.y, o8.y, PRMT_LO); s0.w = __byte_perm(e8.y, o8.y, PRMT_HI);
            s1.x = __byte_perm(e8.z, o8.z, PRMT_LO); s1.y = __byte_perm(e8.z, o8.z, PRMT_HI);
            s1.z = __byte_perm(e8.w, o8.w, PRMT_LO); s1.w = __byte_perm(e8.w, o8.w, PRMT_HI);
            *(uint4*)&xsp[kk][j][4 + q8]     = s0;
            *(uint4*)&xsp[kk][j][4 + q8 + 4] = s1;
        }
    }
    // halo
    if (tid < 48) {
        int kk = tid / 12, rr = tid % 12;
        int j = rr >> 1, side = rr & 1;
        int gy = y0 + j - 1;
        int gx = side ? (x0 + 128) : (x0 - 1);
        uint32_t wd = 0;
        if (gy >= 0 && gy < HH && (unsigned)gx < WW) {
            uint16_t eb = *reinterpret_cast<const uint16_t*>(qbh + (size_t)(2*kk    )*NPIX + gy*WW + gx);
            uint16_t ob = *reinterpret_cast<const uint16_t*>(qbh + (size_t)(2*kk + 1)*NPIX + gy*WW + gx);
            wd = (uint32_t)eb | ((uint32_t)ob << 16);
        }
        xsp[kk][j][side ? 132 : 3] = wd;
    }

    // A frags from g_kv (pp-major K, 5 k16 steps)
    const float* kvb = g_kv + (size_t)(b*HEADS + h)*KVSZ;
    uint32_t Ar[5][4];
    #pragma unroll
    for (int s = 0; s < 5; s++) {
        int ppa = 2*s;
        Ar[s][0] = packbf(kvb[((2*l4    )*9 + ppa)*8 + g],
                          kvb[((2*l4 + 1)*9 + ppa)*8 + g]);
        Ar[s][1] = (g == 0) ? packbf(kvb[576 + (2*l4)*9 + ppa],
                                     kvb[576 + (2*l4 + 1)*9 + ppa]) : 0u;
        if (s < 4) {
            int ppb = ppa + 1;
            Ar[s][2] = packbf(kvb[((2*l4    )*9 + ppb)*8 + g],
                              kvb[((2*l4 + 1)*9 + ppb)*8 + g]);
            Ar[s][3] = (g == 0) ? packbf(kvb[576 + (2*l4)*9 + ppb],
                                         kvb[576 + (2*l4 + 1)*9 + ppb]) : 0u;
        } else {
            Ar[s][2] = 0u; Ar[s][3] = 0u;
        }
    }
    __syncthreads();

    #pragma unroll
    for (int f = 0; f < 8; f++) {
        int nb = xh*64 + f*8 + g;
        float acc[4] = {0.f, 0.f, 0.f, 0.f};
        #pragma unroll
        for (int s = 0; s < 5; s++) {
            int ppa = 2*s;
            int dya = ppa / 3, dxa = ppa % 3;
            uint32_t b0 = xsp[l4][r + dya][3 + nb + dxa];
            uint32_t b1 = b0;
            if (s < 4) {
                int ppb = ppa + 1;
                b1 = xsp[l4][r + ppb/3][3 + nb + ppb%3];
            }
            mma_bf16(acc, Ar[s][0], Ar[s][1], Ar[s][2], Ar[s][3], b0, b1);
        }
        float den0 = __shfl_sync(0xffffffffu, acc[2], l4);
        float den1 = __shfl_sync(0xffffffffu, acc[3], l4);
        float i0 = 1.0f / (den0 + 1e-6f);
        float i1 = 1.0f / (den1 + 1e-6f);
        size_t on = (size_t)(b*C + 8*h + g)*NPIX
                  + (size_t)(y0 + r)*WW + x0 + xh*64 + f*8 + 2*l4;
        *(uint32_t*)&g_o[on] = packbf(acc[0]*i0, acc[1]*i1);
    }
}

// ---------------------------------------------------------------
// depthwise 3x3 conv + bias + gelu; bf16 in/out, 4 px/thread.
// ---------------------------------------------------------------
__global__ __launch_bounds__(256)
void dw_gelu_kernel(const __nv_bfloat16* __restrict__ in,
                    const float* __restrict__ w,
                    const float* __restrict__ bias,
                    __nv_bfloat16* __restrict__ out) {
    int idx = blockIdx.x * 256 + threadIdx.x;
    int n   = idx * 4;
    int x   = n & 255;
    int y   = (n >> 8) & 255;
    int bc  = n >> 16;
    int c   = bc & (C - 1);
    const __nv_bfloat16* ib = in + (size_t)bc*NPIX;

    float bv = bias[c];
    float a[4] = {bv, bv, bv, bv};
    #pragma unroll
    for (int i = 0; i < 3; i++) {
        int yy = y + i - 1;
        if (yy < 0 || yy >= HH) continue;
        const __nv_bfloat16* r = ib + yy*WW;
        float row[6];
        row[0] = (x > 0) ? __bfloat162float(r[x-1]) : 0.f;
        __nv_bfloat162 m0 = *(const __nv_bfloat162*)&r[x];
        __nv_bfloat162 m1 = *(const __nv_bfloat162*)&r[x+2];
        row[1] = __low2float(m0); row[2] = __high2float(m0);
        row[3] = __low2float(m1); row[4] = __high2float(m1);
        row[5] = (x + 4 < WW) ? __bfloat162float(r[x+4]) : 0.f;
        #pragma unroll
        for (int j = 0; j < 3; j++) {
            float wv = w[c*9 + i*3 + j];
            #pragma unroll
            for (int t = 0; t < 4; t++)
                a[t] = fmaf(wv, row[t + j], a[t]);
        }
    }
    uint2 st;
    st.x = packbf(gelu_exact(a[0]), gelu_exact(a[1]));
    st.y = packbf(gelu_exact(a[2]), gelu_exact(a[3]));
    *(uint2*)&out[(size_t)n] = st;
}

// ---------------------------------------------------------------
extern "C" void kernel_launch(void* const* d_in, const int* in_sizes, int n_in,
                              void* d_out, int out_size) {
    const float* x      = (const float*)d_in[0];
    const float* qkv_w  = (const float*)d_in[1];
    const float* qkv_b  = (const float*)d_in[2];
    const float* proj_w = (const float*)d_in[3];
    const float* proj_b = (const float*)d_in[4];
    const float* ffn1_w = (const float*)d_in[5];
    const float* ffn1_b = (const float*)d_in[6];
    const float* dw_w   = (const float*)d_in[7];
    const float* dw_b   = (const float*)d_in[8];
    const float* ffn2_w = (const float*)d_in[9];
    const float* ffn2_b = (const float*)d_in[10];
    float* out = (float*)d_out;

    __nv_bfloat16 *p_o, *p_h1, *p_h2;
    float *p_x1;
    cudaGetSymbolAddress((void**)&p_o,  g_o);
    cudaGetSymbolAddress((void**)&p_x1, g_x1);
    cudaGetSymbolAddress((void**)&p_h1, g_h1);
    cudaGetSymbolAddress((void**)&p_h2, g_h2);

    dim3 gpw(NPIX/128, BATCH);     // (512, 2)

    zero_kv_kernel<<<(BATCH*HEADS*KVSZ + 255)/256, 256>>>();
    pw_qkv_kernel<<<gpw, 256>>>(x, qkv_w, qkv_b);
    kv_kernel<<<dim3(HH/KV_ROWS, BATCH*HEADS), 256>>>();
    attn_kernel<<<dim3(128, HEADS, BATCH), 256>>>();
    proj3x3_kernel<<<gpw, 256>>>(p_o, proj_w, proj_b, x, p_x1);
    pw_gelu_kernel<<<gpw, 256>>>(p_x1, ffn1_w, ffn1_b, p_h1);
    dw_gelu_kernel<<<BATCH*C*NPIX/1024, 256>>>(p_h1, dw_w, dw_b, p_h2);
    pw_res_kernel<<<gpw, 256>>>(p_h2, ffn2_w, ffn2_b, p_x1, out);
}

// round 16
// speedup vs baseline: 4.9581x; 1.9409x over previous
#include <cuda_runtime.h>
#include <cuda_bf16.h>
#include <math.h>
#include <stdint.h>

#define C        64
#define HH       256
#define WW       256
#define NPIX     65536            // HH*WW
#define BATCH    2
#define HEADS    8
#define KVSZ     648              // 72*8 + 72 per (b,h)

// -------- scratch (device globals) --------
__device__ __nv_bfloat16 g_q [BATCH*C*NPIX];
__device__ __nv_bfloat16 g_k [BATCH*C*NPIX];
__device__ __nv_bfloat16 g_v [BATCH*C*NPIX];
__device__ __nv_bfloat16 g_o [BATCH*C*NPIX];
__device__ __nv_bfloat16 g_h1[BATCH*C*NPIX];
__device__ __nv_bfloat16 g_h2[BATCH*C*NPIX];
__device__ float g_x1[BATCH*C*NPIX];
__device__ float g_kv[BATCH*HEADS*KVSZ];

// pre-packed bf16 A-fragments for all GEMM weights
// qkv: [p][grp][s][lane]  (3*4*4*32 = 1536)
// ffn1: +1536 [grp][s][lane] (512) ; ffn2: +2048 (512)
// proj: +2560 [grp][chunk][pp][lane] (4*4*9*32 = 4608)
#define WF_QKV  0
#define WF_F1   1536
#define WF_F2   2048
#define WF_PROJ 2560
#define WF_TOT  7168
__device__ uint4 g_wfrag[WF_TOT];

__device__ __forceinline__ float gelu_exact(float v) {
    return 0.5f * v * (1.0f + erff(v * 0.7071067811865476f));
}

__device__ __forceinline__ uint32_t packbf(float lo, float hi) {
    __nv_bfloat162 t = __floats2bfloat162_rn(lo, hi);   // .x = lo (low 16b)
    return *reinterpret_cast<uint32_t*>(&t);
}

// m16n8k16 bf16 MMA, fp32 accum.
// A row-major: a0={A[g][2l],A[g][2l+1]} a1={A[g+8][..]} a2={A[g][2l+8..]} a3={A[g+8][2l+8..]}
// B col-major: b0={B[2l][g],B[2l+1][g]} b1={B[2l+8][g],B[2l+9][g]}
// C: c0=(g,2l) c1=(g,2l+1) c2=(g+8,2l) c3=(g+8,2l+1)
__device__ __forceinline__ void mma_bf16(float* c,
        uint32_t a0, uint32_t a1, uint32_t a2, uint32_t a3,
        uint32_t b0, uint32_t b1) {
    asm volatile(
        "mma.sync.aligned.m16n8k16.row.col.f32.bf16.bf16.f32 "
        "{%0,%1,%2,%3}, {%4,%5,%6,%7}, {%8,%9}, {%0,%1,%2,%3};\n"
        : "+f"(c[0]), "+f"(c[1]), "+f"(c[2]), "+f"(c[3])
        : "r"(a0), "r"(a1), "r"(a2), "r"(a3), "r"(b0), "r"(b1));
}

#define PRMT_LO 0x5410u
#define PRMT_HI 0x7632u
// {x.hi16, y.lo16}
#define PRMT_SHIFT 0x5432u

// ---------------------------------------------------------------
__global__ void zero_kv_kernel() {
    int i = blockIdx.x * blockDim.x + threadIdx.x;
    if (i < BATCH*HEADS*KVSZ) g_kv[i] = 0.0f;
}

// ---------------------------------------------------------------
// Pre-pack all GEMM weight A-fragments (bf16) into g_wfrag.
// 7168 threads, one uint4 frag each.
// ---------------------------------------------------------------
__global__ __launch_bounds__(256)
void wprep_kernel(const float* __restrict__ qkv_w,
                  const float* __restrict__ ffn1_w,
                  const float* __restrict__ ffn2_w,
                  const float* __restrict__ proj_w) {
    int idx = blockIdx.x * 256 + threadIdx.x;
    if (idx >= WF_TOT) return;
    uint4 fr;
    if (idx < WF_F1) {                       // qkv
        int p = idx / 512, rem = idx % 512;
        int grp = rem / 128, s = (rem >> 5) & 3, lane = rem & 31;
        int g = lane >> 2, l4 = lane & 3;
        const float* wp = qkv_w + (size_t)(p*64 + grp*16 + g)*64;
        int k = 16*s + 2*l4;
        fr.x = packbf(wp[k],        wp[k+1]);
        fr.y = packbf(wp[8*64+k],   wp[8*64+k+1]);
        fr.z = packbf(wp[k+8],      wp[k+9]);
        fr.w = packbf(wp[8*64+k+8], wp[8*64+k+9]);
    } else if (idx < WF_PROJ) {              // ffn1 / ffn2
        const float* wb = (idx < WF_F2) ? ffn1_w : ffn2_w;
        int j = (idx < WF_F2) ? idx - WF_F1 : idx - WF_F2;
        int grp = j / 128, s = (j >> 5) & 3, lane = j & 31;
        int g = lane >> 2, l4 = lane & 3;
        const float* wp = wb + (size_t)(grp*16 + g)*64;
        int k = 16*s + 2*l4;
        fr.x = packbf(wp[k],        wp[k+1]);
        fr.y = packbf(wp[8*64+k],   wp[8*64+k+1]);
        fr.z = packbf(wp[k+8],      wp[k+9]);
        fr.w = packbf(wp[8*64+k+8], wp[8*64+k+9]);
    } else {                                 // proj
        int j = idx - WF_PROJ;
        int grp = j / 1152, rem = j % 1152;
        int chunk = rem / 288, rem2 = rem % 288;
        int pp = rem2 >> 5, lane = rem2 & 31;
        int g = lane >> 2, l4 = lane & 3;
        const float* wb0 = proj_w + (size_t)(grp*16 + g)*576 + pp;
        const float* wb1 = wb0 + 8*576;
        int ic0 = chunk*16;
        fr.x = packbf(wb0[(ic0 + 2*l4    )*9], wb0[(ic0 + 2*l4 + 1)*9]);
        fr.y = packbf(wb1[(ic0 + 2*l4    )*9], wb1[(ic0 + 2*l4 + 1)*9]);
        fr.z = packbf(wb0[(ic0 + 2*l4 + 8)*9], wb0[(ic0 + 2*l4 + 9)*9]);
        fr.w = packbf(wb1[(ic0 + 2*l4 + 8)*9], wb1[(ic0 + 2*l4 + 9)*9]);
    }
    g_wfrag[idx] = fr;
}

// ---------------------------------------------------------------
// Fused qkv pointwise GEMM (bf16 MMA): fp32 x in, bf16 q/k/v out.
// ---------------------------------------------------------------
__global__ __launch_bounds__(256)
void pw_qkv_kernel(const float* __restrict__ x,
                   const float* __restrict__ bias) {
    __shared__ uint32_t xsp[C/2][136];      // 17.4 KB

    int b    = blockIdx.y;
    int pix0 = blockIdx.x * 128;
    int tid  = threadIdx.x;
    const float* inb = x + (size_t)b*C*NPIX + pix0;

    #pragma unroll
    for (int it = 0; it < 4; it++) {
        int idx = tid + it*256;
        int kk = idx >> 5, p4 = (idx & 31) << 2;
        float4 e = *(const float4*)(inb + (size_t)(2*kk    )*NPIX + p4);
        float4 o = *(const float4*)(inb + (size_t)(2*kk + 1)*NPIX + p4);
        uint4 st;
        st.x = packbf(e.x, o.x); st.y = packbf(e.y, o.y);
        st.z = packbf(e.z, o.z); st.w = packbf(e.w, o.w);
        *(uint4*)&xsp[kk][p4] = st;
    }
    __syncthreads();

    int lane = tid & 31, wid = tid >> 5;
    int g = lane >> 2, l4 = lane & 3;
    int grp = wid & 3;
    int oc0 = grp * 16;
    int pxw = (wid >> 2) * 64;

    #pragma unroll
    for (int p = 0; p < 3; p++) {
        __nv_bfloat16* op = ((p == 0) ? g_q : (p == 1) ? g_k : g_v)
                          + (size_t)b*C*NPIX + pix0;
        uint4 Ar[4];
        #pragma unroll
        for (int s = 0; s < 4; s++)
            Ar[s] = g_wfrag[WF_QKV + ((p*4 + grp)*4 + s)*32 + lane];
        float b_lo = bias[p*C + oc0 + g];
        float b_hi = bias[p*C + oc0 + g + 8];

        #pragma unroll
        for (int f = 0; f < 8; f++) {
            int px0f = pxw + f*8;
            float acc[4] = {0.f, 0.f, 0.f, 0.f};
            #pragma unroll
            for (int s = 0; s < 4; s++) {
                uint32_t b0 = xsp[s*8 + l4    ][px0f + g];
                uint32_t b1 = xsp[s*8 + l4 + 4][px0f + g];
                mma_bf16(acc, Ar[s].x, Ar[s].y, Ar[s].z, Ar[s].w, b0, b1);
            }
            float v0 = acc[0] + b_lo, v1 = acc[1] + b_lo;
            float v2 = acc[2] + b_hi, v3 = acc[3] + b_hi;
            if (p < 2) {
                v0 = fmaxf(v0, 0.f); v1 = fmaxf(v1, 0.f);
                v2 = fmaxf(v2, 0.f); v3 = fmaxf(v3, 0.f);
            }
            size_t olo = (size_t)(oc0 + g)*NPIX + px0f + 2*l4;
            *(uint32_t*)&op[olo]          = packbf(v0, v1);
            *(uint32_t*)&op[olo + 8*NPIX] = packbf(v2, v3);
        }
    }
}

// ---------------------------------------------------------------
// ffn1: fp32 x1 in -> gelu -> bf16 h1 out  (bf16 MMA)
// ---------------------------------------------------------------
__global__ __launch_bounds__(256)
void pw_gelu_kernel(const float* __restrict__ in,
                    const float* __restrict__ bias,
                    __nv_bfloat16* __restrict__ out) {
    __shared__ uint32_t xsp[C/2][136];

    int b    = blockIdx.y;
    int pix0 = blockIdx.x * 128;
    int tid  = threadIdx.x;
    const float* inb = in + (size_t)b*C*NPIX + pix0;

    #pragma unroll
    for (int it = 0; it < 4; it++) {
        int idx = tid + it*256;
        int kk = idx >> 5, p4 = (idx & 31) << 2;
        float4 e = *(const float4*)(inb + (size_t)(2*kk    )*NPIX + p4);
        float4 o = *(const float4*)(inb + (size_t)(2*kk + 1)*NPIX + p4);
        uint4 st;
        st.x = packbf(e.x, o.x); st.y = packbf(e.y, o.y);
        st.z = packbf(e.z, o.z); st.w = packbf(e.w, o.w);
        *(uint4*)&xsp[kk][p4] = st;
    }
    __syncthreads();

    int lane = tid & 31, wid = tid >> 5;
    int g = lane >> 2, l4 = lane & 3;
    int grp = wid & 3;
    int oc0 = grp * 16;
    int pxw = (wid >> 2) * 64;

    uint4 Ar[4];
    #pragma unroll
    for (int s = 0; s < 4; s++)
        Ar[s] = g_wfrag[WF_F1 + (grp*4 + s)*32 + lane];
    float b_lo = bias[oc0 + g];
    float b_hi = bias[oc0 + g + 8];
    __nv_bfloat16* op = out + (size_t)b*C*NPIX + pix0;

    #pragma unroll
    for (int f = 0; f < 8; f++) {
        int px0f = pxw + f*8;
        float acc[4] = {0.f, 0.f, 0.f, 0.f};
        #pragma unroll
        for (int s = 0; s < 4; s++) {
            uint32_t b0 = xsp[s*8 + l4    ][px0f + g];
            uint32_t b1 = xsp[s*8 + l4 + 4][px0f + g];
            mma_bf16(acc, Ar[s].x, Ar[s].y, Ar[s].z, Ar[s].w, b0, b1);
        }
        float v0 = gelu_exact(acc[0] + b_lo);
        float v1 = gelu_exact(acc[1] + b_lo);
        float v2 = gelu_exact(acc[2] + b_hi);
        float v3 = gelu_exact(acc[3] + b_hi);
        size_t olo = (size_t)(oc0 + g)*NPIX + px0f + 2*l4;
        *(uint32_t*)&op[olo]          = packbf(v0, v1);
        *(uint32_t*)&op[olo + 8*NPIX] = packbf(v2, v3);
    }
}

// ---------------------------------------------------------------
// ffn2: bf16 h2 in + fp32 res -> fp32 out  (bf16 MMA)
// ---------------------------------------------------------------
__global__ __launch_bounds__(256)
void pw_res_kernel(const __nv_bfloat16* __restrict__ in,
                   const float* __restrict__ bias,
                   const float* __restrict__ res,
                   float* __restrict__ out) {
    __shared__ uint32_t xsp[C/2][136];

    int b    = blockIdx.y;
    int pix0 = blockIdx.x * 128;
    int tid  = threadIdx.x;
    const __nv_bfloat16* inb = in + (size_t)b*C*NPIX + pix0;

    #pragma unroll
    for (int it = 0; it < 2; it++) {
        int idx = tid + it*256;
        int kk = idx >> 4, q8 = (idx & 15) << 3;
        uint4 e8 = *(const uint4*)(inb + (size_t)(2*kk    )*NPIX + q8);
        uint4 o8 = *(const uint4*)(inb + (size_t)(2*kk + 1)*NPIX + q8);
        uint4 s0, s1;
        s0.x = __byte_perm(e8.x, o8.x, PRMT_LO); s0.y = __byte_perm(e8.x, o8.x, PRMT_HI);
        s0.z = __byte_perm(e8.y, o8.y, PRMT_LO); s0.w = __byte_perm(e8.y, o8.y, PRMT_HI);
        s1.x = __byte_perm(e8.z, o8.z, PRMT_LO); s1.y = __byte_perm(e8.z, o8.z, PRMT_HI);
        s1.z = __byte_perm(e8.w, o8.w, PRMT_LO); s1.w = __byte_perm(e8.w, o8.w, PRMT_HI);
        *(uint4*)&xsp[kk][q8]     = s0;
        *(uint4*)&xsp[kk][q8 + 4] = s1;
    }
    __syncthreads();

    int lane = tid & 31, wid = tid >> 5;
    int g = lane >> 2, l4 = lane & 3;
    int grp = wid & 3;
    int oc0 = grp * 16;
    int pxw = (wid >> 2) * 64;

    uint4 Ar[4];
    #pragma unroll
    for (int s = 0; s < 4; s++)
        Ar[s] = g_wfrag[WF_F2 + (grp*4 + s)*32 + lane];
    float b_lo = bias[oc0 + g];
    float b_hi = bias[oc0 + g + 8];
    float* op = out + (size_t)b*C*NPIX + pix0;
    const float* rp = res + (size_t)b*C*NPIX + pix0;

    #pragma unroll
    for (int f = 0; f < 8; f++) {
        int px0f = pxw + f*8;
        float acc[4] = {0.f, 0.f, 0.f, 0.f};
        #pragma unroll
        for (int s = 0; s < 4; s++) {
            uint32_t b0 = xsp[s*8 + l4    ][px0f + g];
            uint32_t b1 = xsp[s*8 + l4 + 4][px0f + g];
            mma_bf16(acc, Ar[s].x, Ar[s].y, Ar[s].z, Ar[s].w, b0, b1);
        }
        size_t olo = (size_t)(oc0 + g)*NPIX + px0f + 2*l4;
        size_t ohi = olo + 8*NPIX;
        float v0 = acc[0] + b_lo + rp[olo];
        float v1 = acc[1] + b_lo + rp[olo+1];
        float v2 = acc[2] + b_hi + rp[ohi];
        float v3 = acc[3] + b_hi + rp[ohi+1];
        *(float2*)&op[olo] = make_float2(v0, v1);
        *(float2*)&op[ohi] = make_float2(v2, v3);
    }
}

// ---------------------------------------------------------------
// proj 3x3 conv (bf16 o in, fp32 res/out): x1 = x + proj(o)
// ---------------------------------------------------------------
__global__ __launch_bounds__(256)
void proj3x3_kernel(const __nv_bfloat16* __restrict__ in,
                    const float* __restrict__ bias,
                    const float* __restrict__ res,
                    float* __restrict__ out) {
    __shared__ uint32_t xsp[8][3][136];     // 13 KB

    int b  = blockIdx.y;
    int y  = blockIdx.x >> 1;
    int x0 = (blockIdx.x & 1) << 7;
    int tid = threadIdx.x;
    int lane = tid & 31, wid = tid >> 5;
    int g = lane >> 2, l4 = lane & 3;
    int grp = wid & 3;
    int oc0 = grp * 16;
    int pxw = (wid >> 2) * 64;

    const __nv_bfloat16* inb = in + (size_t)b*C*NPIX;

    float acc[8][4];
    #pragma unroll
    for (int f = 0; f < 8; f++)
        #pragma unroll
        for (int j = 0; j < 4; j++) acc[f][j] = 0.f;

    #pragma unroll 1
    for (int chunk = 0; chunk < 4; chunk++) {
        int ic0 = chunk * 16;
        __syncthreads();
        #pragma unroll
        for (int it = 0; it < 2; it++) {
            int idx = tid + it*256;
            if (idx < 384) {
                int icp = idx / 48;
                int rr  = idx % 48;
                int dy  = rr / 16;
                int q8  = (rr & 15) << 3;
                int gy = y + dy - 1;
                uint4 e8 = make_uint4(0,0,0,0), o8 = make_uint4(0,0,0,0);
                if (gy >= 0 && gy < HH) {
                    e8 = *(const uint4*)(inb + (size_t)(ic0 + 2*icp    )*NPIX + gy*WW + x0 + q8);
                    o8 = *(const uint4*)(inb + (size_t)(ic0 + 2*icp + 1)*NPIX + gy*WW + x0 + q8);
                }
                uint4 s0, s1;
                s0.x = __byte_perm(e8.x, o8.x, PRMT_LO); s0.y = __byte_perm(e8.x, o8.x, PRMT_HI);
                s0.z = __byte_perm(e8.y, o8.y, PRMT_LO); s0.w = __byte_perm(e8.y, o8.y, PRMT_HI);
                s1.x = __byte_perm(e8.z, o8.z, PRMT_LO); s1.y = __byte_perm(e8.z, o8.z, PRMT_HI);
                s1.z = __byte_perm(e8.w, o8.w, PRMT_LO); s1.w = __byte_perm(e8.w, o8.w, PRMT_HI);
                *(uint4*)&xsp[icp][dy][4 + q8]     = s0;
                *(uint4*)&xsp[icp][dy][4 + q8 + 4] = s1;
            }
        }
        if (tid < 48) {
            int icp = tid / 6, r = tid % 6;
            int dy = r >> 1, side = r & 1;
            int gy = y + dy - 1;
            int gx = side ? (x0 + 128) : (x0 - 1);
            uint32_t wd = 0;
            if (gy >= 0 && gy < HH && (unsigned)gx < WW) {
                uint16_t eb = *reinterpret_cast<const uint16_t*>(inb + (size_t)(ic0 + 2*icp    )*NPIX + gy*WW + gx);
                uint16_t ob = *reinterpret_cast<const uint16_t*>(inb + (size_t)(ic0 + 2*icp + 1)*NPIX + gy*WW + gx);
                wd = (uint32_t)eb | ((uint32_t)ob << 16);
            }
            xsp[icp][dy][side ? 132 : 3] = wd;
        }
        __syncthreads();

        #pragma unroll
        for (int pp = 0; pp < 9; pp++) {
            int dy = pp / 3, dx = pp % 3;
            uint4 Af = g_wfrag[WF_PROJ + ((grp*4 + chunk)*9 + pp)*32 + lane];
            #pragma unroll
            for (int f = 0; f < 8; f++) {
                int xb = 3 + pxw + f*8 + g + dx;
                uint32_t b0 = xsp[l4    ][dy][xb];
                uint32_t b1 = xsp[l4 + 4][dy][xb];
                mma_bf16(acc[f], Af.x, Af.y, Af.z, Af.w, b0, b1);
            }
        }
    }

    float b_lo = bias[oc0 + g];
    float b_hi = bias[oc0 + g + 8];
    size_t pbase = (size_t)b*C*NPIX + (size_t)y*WW + x0;
    #pragma unroll
    for (int f = 0; f < 8; f++) {
        int px = pxw + f*8 + 2*l4;
        size_t olo = pbase + (size_t)(oc0 + g)*NPIX + px;
        size_t ohi = olo + 8*NPIX;
        float v0 = acc[f][0] + b_lo + res[olo];
        float v1 = acc[f][1] + b_lo + res[olo+1];
        float v2 = acc[f][2] + b_hi + res[ohi];
        float v3 = acc[f][3] + b_hi + res[ohi+1];
        *(float2*)&out[olo] = make_float2(v0, v1);
        *(float2*)&out[ohi] = make_float2(v2, v3);
    }
}

// ---------------------------------------------------------------
// kv via bf16 MMA: kv[d,e] = sum_n ku[d,n]*v[e,n], ksum via ones-row.
// A rows: 0..7 = v channels (e), row 8 = 1.0 (ksum), 9..15 = 0.
// B cols: n = cl (channel g), k = pixel; shifted-k windows per pp.
// Warp = one row y of one (b,h); 16 ksteps x 9 pp MMAs; atomic reduce.
// grid (32, BATCH*HEADS), block 256 (8 warps = 8 rows).
// ---------------------------------------------------------------
__global__ __launch_bounds__(256)
void kv_mma_kernel() {
    int bh = blockIdx.y;
    int b = bh >> 3, h = bh & 7;
    int w = threadIdx.x >> 5, lane = threadIdx.x & 31;
    int g = lane >> 2, l4 = lane & 3;
    int y = blockIdx.x * 8 + w;

    const __nv_bfloat16* kr0 = g_k + ((size_t)(b*C + 8*h + g))*NPIX;
    const __nv_bfloat16* vr  = g_v + ((size_t)(b*C + 8*h + g))*NPIX + (size_t)y*WW;

    float acc[9][4];
    #pragma unroll
    for (int pp = 0; pp < 9; pp++)
        #pragma unroll
        for (int j = 0; j < 4; j++) acc[pp][j] = 0.f;

    uint32_t ones = (g == 0) ? 0x3F803F80u : 0u;

    #pragma unroll 1
    for (int t = 0; t < 16; t++) {
        int p = t*16 + 2*l4;
        uint32_t a0 = *(const uint32_t*)(vr + p);
        uint32_t a2 = *(const uint32_t*)(vr + p + 8);
        #pragma unroll
        for (int dy = 0; dy < 3; dy++) {
            int yy = y + dy - 1;
            bool rv = (yy >= 0 && yy < HH);
            const __nv_bfloat16* kr = kr0 + (size_t)yy*WW;
            uint32_t Lw = 0, Aw = 0, Rw = 0, L1 = 0, A1 = 0, R1 = 0;
            if (rv) {
                Aw = *(const uint32_t*)(kr + p);
                Rw = *(const uint32_t*)(kr + p + 2);
                L1 = *(const uint32_t*)(kr + p + 6);
                A1 = *(const uint32_t*)(kr + p + 8);
                if (p >= 2)       Lw = *(const uint32_t*)(kr + p - 2);
                if (p + 10 < WW)  R1 = *(const uint32_t*)(kr + p + 10);
            }
            uint32_t b0_0 = __byte_perm(Lw, Aw, PRMT_SHIFT);   // {p-1, p}
            uint32_t b1_0 = __byte_perm(L1, A1, PRMT_SHIFT);   // {p+7, p+8}
            uint32_t b0_2 = __byte_perm(Aw, Rw, PRMT_SHIFT);   // {p+1, p+2}
            uint32_t b1_2 = __byte_perm(A1, R1, PRMT_SHIFT);   // {p+9, p+10}
            mma_bf16(acc[dy*3 + 0], a0, ones, a2, ones, b0_0, b1_0);
            mma_bf16(acc[dy*3 + 1], a0, ones, a2, ones, Aw,   A1);
            mma_bf16(acc[dy*3 + 2], a0, ones, a2, ones, b0_2, b1_2);
        }
    }

    float* outp = g_kv + bh*KVSZ;
    #pragma unroll
    for (int pp = 0; pp < 9; pp++) {
        atomicAdd(&outp[((2*l4    )*9 + pp)*8 + g], acc[pp][0]);
        atomicAdd(&outp[((2*l4 + 1)*9 + pp)*8 + g], acc[pp][1]);
        if (g == 0) {
            atomicAdd(&outp[576 + (2*l4    )*9 + pp], acc[pp][2]);
            atomicAdd(&outp[576 + (2*l4 + 1)*9 + pp], acc[pp][3]);
        }
    }
}

// ---------------------------------------------------------------
// Attention readout as bf16 MMA 3x3 conv (q bf16 in, o bf16 out).
// ---------------------------------------------------------------
__global__ __launch_bounds__(256)
void attn_kernel() {
    __shared__ __align__(16) uint32_t xsp[4][6][140];   // 13.4 KB

    int b  = blockIdx.z;
    int h  = blockIdx.y;
    int y0 = (blockIdx.x >> 1) * 4;
    int x0 = (blockIdx.x & 1) << 7;
    int tid = threadIdx.x;
    int lane = tid & 31, wid = tid >> 5;
    int g = lane >> 2, l4 = lane & 3;
    int r  = wid >> 1;
    int xh = wid & 1;

    const __nv_bfloat16* qbh = g_q + ((size_t)(b*C + 8*h))*NPIX;

    #pragma unroll
    for (int it = 0; it < 2; it++) {
        int idx = tid + it*256;
        if (idx < 384) {
            int kk = idx / 96;
            int rr = idx % 96;
            int j  = rr / 16;
            int q8 = (rr & 15) << 3;
            int gy = y0 + j - 1;
            uint4 e8 = make_uint4(0,0,0,0), o8 = make_uint4(0,0,0,0);
            if (gy >= 0 && gy < HH) {
                e8 = *(const uint4*)(qbh + (size_t)(2*kk    )*NPIX + gy*WW + x0 + q8);
                o8 = *(const uint4*)(qbh + (size_t)(2*kk + 1)*NPIX + gy*WW + x0 + q8);
            }
            uint4 s0, s1;
            s0.x = __byte_perm(e8.x, o8.x, PRMT_LO); s0.y = __byte_perm(e8.x, o8.x, PRMT_HI);
            s0.z = __byte_perm(e8.y, o8.y, PRMT_LO); s0.w = __byte_perm(e8.y, o8.y, PRMT_HI);
            s1.x = __byte_perm(e8.z, o8.z, PRMT_LO); s1.y = __byte_perm(e8.z, o8.z, PRMT_HI);
            s1.z = __byte_perm(e8.w, o8.w, PRMT_LO); s1.w = __byte_perm(e8.w, o8.w, PRMT_HI);
            *(uint4*)&xsp[kk][j][4 + q8]     = s0;
            *(uint4*)&xsp[kk][j][4 + q8 + 4] = s1;
        }
    }
    if (tid < 48) {
        int kk = tid / 12, rr = tid % 12;
        int j = rr >> 1, side = rr & 1;
        int gy = y0 + j - 1;
        int gx = side ? (x0 + 128) : (x0 - 1);
        uint32_t wd = 0;
        if (gy >= 0 && gy < HH && (unsigned)gx < WW) {
            uint16_t eb = *reinterpret_cast<const uint16_t*>(qbh + (size_t)(2*kk    )*NPIX + gy*WW + gx);
            uint16_t ob = *reinterpret_cast<const uint16_t*>(qbh + (size_t)(2*kk + 1)*NPIX + gy*WW + gx);
            wd = (uint32_t)eb | ((uint32_t)ob << 16);
        }
        xsp[kk][j][side ? 132 : 3] = wd;
    }

    const float* kvb = g_kv + (size_t)(b*HEADS + h)*KVSZ;
    uint32_t Ar[5][4];
    #pragma unroll
    for (int s = 0; s < 5; s++) {
        int ppa = 2*s;
        Ar[s][0] = packbf(kvb[((2*l4    )*9 + ppa)*8 + g],
                          kvb[((2*l4 + 1)*9 + ppa)*8 + g]);
        Ar[s][1] = (g == 0) ? packbf(kvb[576 + (2*l4)*9 + ppa],
                                     kvb[576 + (2*l4 + 1)*9 + ppa]) : 0u;
        if (s < 4) {
            int ppb = ppa + 1;
            Ar[s][2] = packbf(kvb[((2*l4    )*9 + ppb)*8 + g],
                              kvb[((2*l4 + 1)*9 + ppb)*8 + g]);
            Ar[s][3] = (g == 0) ? packbf(kvb[576 + (2*l4)*9 + ppb],
                                         kvb[576 + (2*l4 + 1)*9 + ppb]) : 0u;
        } else {
            Ar[s][2] = 0u; Ar[s][3] = 0u;
        }
    }
    __syncthreads();

    #pragma unroll
    for (int f = 0; f < 8; f++) {
        int nb = xh*64 + f*8 + g;
        float acc[4] = {0.f, 0.f, 0.f, 0.f};
        #pragma unroll
        for (int s = 0; s < 5; s++) {
            int ppa = 2*s;
            int dya = ppa / 3, dxa = ppa % 3;
            uint32_t b0 = xsp[l4][r + dya][3 + nb + dxa];
            uint32_t b1 = b0;
            if (s < 4) {
                int ppb = ppa + 1;
                b1 = xsp[l4][r + ppb/3][3 + nb + ppb%3];
            }
            mma_bf16(acc, Ar[s][0], Ar[s][1], Ar[s][2], Ar[s][3], b0, b1);
        }
        float den0 = __shfl_sync(0xffffffffu, acc[2], l4);
        float den1 = __shfl_sync(0xffffffffu, acc[3], l4);
        float i0 = 1.0f / (den0 + 1e-6f);
        float i1 = 1.0f / (den1 + 1e-6f);
        size_t on = (size_t)(b*C + 8*h + g)*NPIX
                  + (size_t)(y0 + r)*WW + x0 + xh*64 + f*8 + 2*l4;
        *(uint32_t*)&g_o[on] = packbf(acc[0]*i0, acc[1]*i1);
    }
}

// ---------------------------------------------------------------
// depthwise 3x3 conv + bias + gelu; bf16 in/out, 4 px/thread.
// ---------------------------------------------------------------
__global__ __launch_bounds__(256)
void dw_gelu_kernel(const __nv_bfloat16* __restrict__ in,
                    const float* __restrict__ w,
                    const float* __restrict__ bias,
                    __nv_bfloat16* __restrict__ out) {
    int idx = blockIdx.x * 256 + threadIdx.x;
    int n   = idx * 4;
    int x   = n & 255;
    int y   = (n >> 8) & 255;
    int bc  = n >> 16;
    int c   = bc & (C - 1);
    const __nv_bfloat16* ib = in + (size_t)bc*NPIX;

    float bv = bias[c];
    float a[4] = {bv, bv, bv, bv};
    #pragma unroll
    for (int i = 0; i < 3; i++) {
        int yy = y + i - 1;
        if (yy < 0 || yy >= HH) continue;
        const __nv_bfloat16* r = ib + yy*WW;
        float row[6];
        row[0] = (x > 0) ? __bfloat162float(r[x-1]) : 0.f;
        __nv_bfloat162 m0 = *(const __nv_bfloat162*)&r[x];
        __nv_bfloat162 m1 = *(const __nv_bfloat162*)&r[x+2];
        row[1] = __low2float(m0); row[2] = __high2float(m0);
        row[3] = __low2float(m1); row[4] = __high2float(m1);
        row[5] = (x + 4 < WW) ? __bfloat162float(r[x+4]) : 0.f;
        #pragma unroll
        for (int j = 0; j < 3; j++) {
            float wv = w[c*9 + i*3 + j];
            #pragma unroll
            for (int t = 0; t < 4; t++)
                a[t] = fmaf(wv, row[t + j], a[t]);
        }
    }
    uint2 st;
    st.x = packbf(gelu_exact(a[0]), gelu_exact(a[1]));
    st.y = packbf(gelu_exact(a[2]), gelu_exact(a[3]));
    *(uint2*)&out[(size_t)n] = st;
}

// ---------------------------------------------------------------
extern "C" void kernel_launch(void* const* d_in, const int* in_sizes, int n_in,
                              void* d_out, int out_size) {
    const float* x      = (const float*)d_in[0];
    const float* qkv_w  = (const float*)d_in[1];
    const float* qkv_b  = (const float*)d_in[2];
    const float* proj_w = (const float*)d_in[3];
    const float* proj_b = (const float*)d_in[4];
    const float* ffn1_w = (const float*)d_in[5];
    const float* ffn1_b = (const float*)d_in[6];
    const float* dw_w   = (const float*)d_in[7];
    const float* dw_b   = (const float*)d_in[8];
    const float* ffn2_w = (const float*)d_in[9];
    const float* ffn2_b = (const float*)d_in[10];
    float* out = (float*)d_out;

    __nv_bfloat16 *p_o, *p_h1, *p_h2;
    float *p_x1;
    cudaGetSymbolAddress((void**)&p_o,  g_o);
    cudaGetSymbolAddress((void**)&p_x1, g_x1);
    cudaGetSymbolAddress((void**)&p_h1, g_h1);
    cudaGetSymbolAddress((void**)&p_h2, g_h2);

    dim3 gpw(NPIX/128, BATCH);     // (512, 2)

    zero_kv_kernel<<<(BATCH*HEADS*KVSZ + 255)/256, 256>>>();
    wprep_kernel<<<WF_TOT/256, 256>>>(qkv_w, ffn1_w, ffn2_w, proj_w);
    pw_qkv_kernel<<<gpw, 256>>>(x, qkv_b);
    kv_mma_kernel<<<dim3(32, BATCH*HEADS), 256>>>();
    attn_kernel<<<dim3(128, HEADS, BATCH), 256>>>();
    proj3x3_kernel<<<gpw, 256>>>(p_o, proj_b, x, p_x1);
    pw_gelu_kernel<<<gpw, 256>>>(p_x1, ffn1_b, p_h1);
    dw_gelu_kernel<<<BATCH*C*NPIX/1024, 256>>>(p_h1, dw_w, dw_b, p_h2);
    pw_res_kernel<<<gpw, 256>>>(p_h2, ffn2_b, p_x1, out);
}